// round 10
// baseline (speedup 1.0000x reference)
#include <cuda_runtime.h>
#include <cstdint>
#include <math.h>

#define D_MODEL 1024
#define SEQ     2048
#define BATCH   2
#define NHEAD   16
#define HD      64
#define MTOT    (BATCH * SEQ)   // 4096
#define BH      (BATCH * NHEAD) // 32

// ---- GEMM tiling (tf32 mma.sync) ----
#define BM 128
#define BN 128
#define BK 32
#define KI (D_MODEL / BK)        // 32
#define AS_STRIDE 40
#define BS_STRIDE 136
#define AS_FLOATS (BM * AS_STRIDE)
#define BS_FLOATS (BK * BS_STRIDE)
#define STAGE_FLOATS (AS_FLOATS + BS_FLOATS)
#define GEMM_SMEM (2 * STAGE_FLOATS * 4)

// ---- attention tiling ----
#define AQ 128                   // q-rows per CTA
#define AK 64                    // keys per k-tile
#define NT (SEQ / AK)            // 32 tiles
#define KS_STRIDE 68
#define VS_STRIDE 72
#define PS_STRIDE 68
#define KS_TILE (AK * KS_STRIDE)             // 4352 floats
#define VS_TILE (AK * VS_STRIDE)             // 4608 floats
#define ATTN_SMEM ((2 * KS_TILE + 2 * VS_TILE + AQ * PS_STRIDE) * 4) // 106496 B

// ---- scratch ----
__device__ __align__(1024) float g_Q[(size_t)BH * SEQ * HD];
__device__ __align__(1024) float g_K[(size_t)BH * SEQ * HD];
__device__ __align__(1024) float g_V[(size_t)BH * SEQ * HD];
__device__ __align__(1024) float g_A[(size_t)MTOT * D_MODEL];
__device__ __align__(1024) float g_Xc[(size_t)MTOT * D_MODEL];
__device__ __align__(1024) float g_Wc[(size_t)D_MODEL * D_MODEL];

__device__ __forceinline__ uint32_t s2u(const void* p) {
    uint32_t a;
    asm("{ .reg .u64 t; cvta.to.shared.u64 t, %1; cvt.u32.u64 %0, t; }" : "=r"(a) : "l"(p));
    return a;
}
__device__ __forceinline__ float rna(float x) {
    asm("cvt.rna.tf32.f32 %0, %0;" : "+f"(x));
    return x;
}

#define CP_ASYNC16(dst, src) \
    asm volatile("cp.async.ca.shared.global [%0], [%1], 16;" :: "r"(dst), "l"(src) : "memory")
#define CP_COMMIT()  asm volatile("cp.async.commit_group;" ::: "memory")
#define CP_WAIT(N)   asm volatile("cp.async.wait_group %0;" :: "n"(N) : "memory")

__device__ __forceinline__ void mma_tf32(float* d, const uint32_t* a, const uint32_t* b) {
    asm volatile(
        "mma.sync.aligned.m16n8k8.row.col.f32.tf32.tf32.f32 "
        "{%0,%1,%2,%3}, {%4,%5,%6,%7}, {%8,%9}, {%0,%1,%2,%3};"
        : "+f"(d[0]), "+f"(d[1]), "+f"(d[2]), "+f"(d[3])
        : "r"(a[0]), "r"(a[1]), "r"(a[2]), "r"(a[3]), "r"(b[0]), "r"(b[1]));
}

// ---------------------------------------------------------------------------
__global__ void __launch_bounds__(256) cvt_tf32(const float4* __restrict__ src,
                                                float4* __restrict__ dst, int n4)
{
    const int i = blockIdx.x * 256 + threadIdx.x;
    if (i < n4) {
        float4 v = src[i];
        v.x = rna(v.x); v.y = rna(v.y); v.z = rna(v.z); v.w = rna(v.w);
        dst[i] = v;
    }
}

// ---------------------------------------------------------------------------
// tf32 mma.sync GEMM. MODE 0: row-major out (plain fp32).
// MODE 1: scatter to [bh, t, hd] with rna((acc + bias) * scale) — pre-rounds
// Q/K/V for the attention kernel (Q additionally folds the 0.125 softmax scale).
// ---------------------------------------------------------------------------
template <int MODE>
__global__ void __launch_bounds__(128) gemm_tc(
    const float* __restrict__ A, const float* __restrict__ W,
    const float* __restrict__ bias, float* __restrict__ out, float scale)
{
    extern __shared__ __align__(16) float smem[];
    float* As[2] = { smem, smem + STAGE_FLOATS };
    float* Bs[2] = { smem + AS_FLOATS, smem + STAGE_FLOATS + AS_FLOATS };

    const int tid = threadIdx.x;
    const int wid = tid >> 5, lane = tid & 31;
    const int wm = wid >> 1, wn = wid & 1;
    const int grp = lane >> 2, tg = lane & 3;
    const int nblk = blockIdx.x, mblk = blockIdx.y;

    const float* Ag = A + (size_t)mblk * BM * D_MODEL;
    const float* Wg = W + nblk * BN;

    auto load_stage = [&](int s, int k0) {
        float* as = As[s];
        float* bs = Bs[s];
#pragma unroll
        for (int j = 0; j < 8; j++) {
            const int c = tid + j * 128;
            const int r = c >> 3, q = c & 7;
            CP_ASYNC16(s2u(&as[r * AS_STRIDE + q * 4]),
                       &Ag[(size_t)r * D_MODEL + k0 + q * 4]);
        }
#pragma unroll
        for (int j = 0; j < 8; j++) {
            const int c = tid + j * 128;
            const int r = c >> 5, q = c & 31;
            CP_ASYNC16(s2u(&bs[r * BS_STRIDE + q * 4]),
                       &Wg[(size_t)(k0 + r) * D_MODEL + q * 4]);
        }
        CP_COMMIT();
    };

    float acc[4][8][4];
#pragma unroll
    for (int i = 0; i < 4; i++)
#pragma unroll
        for (int j = 0; j < 8; j++)
#pragma unroll
            for (int r = 0; r < 4; r++) acc[i][j][r] = 0.0f;

    load_stage(0, 0);

    for (int kt = 0; kt < KI; kt++) {
        if (kt + 1 < KI) {
            load_stage((kt + 1) & 1, (kt + 1) * BK);
            CP_WAIT(1);
        } else {
            CP_WAIT(0);
        }
        __syncthreads();

        const float* as = As[kt & 1];
        const float* bs = Bs[kt & 1];
#pragma unroll
        for (int kk = 0; kk < BK; kk += 8) {
            uint32_t af[4][4], bf[8][2];
#pragma unroll
            for (int mi = 0; mi < 4; mi++) {
                const int r0 = wm * 64 + mi * 16 + grp;
                af[mi][0] = __float_as_uint(as[r0 * AS_STRIDE + kk + tg]);
                af[mi][1] = __float_as_uint(as[(r0 + 8) * AS_STRIDE + kk + tg]);
                af[mi][2] = __float_as_uint(as[r0 * AS_STRIDE + kk + tg + 4]);
                af[mi][3] = __float_as_uint(as[(r0 + 8) * AS_STRIDE + kk + tg + 4]);
            }
#pragma unroll
            for (int nj = 0; nj < 8; nj++) {
                const int n0 = wn * 64 + nj * 8 + grp;
                bf[nj][0] = __float_as_uint(bs[(kk + tg) * BS_STRIDE + n0]);
                bf[nj][1] = __float_as_uint(bs[(kk + tg + 4) * BS_STRIDE + n0]);
            }
#pragma unroll
            for (int mi = 0; mi < 4; mi++)
#pragma unroll
                for (int nj = 0; nj < 8; nj++)
                    mma_tf32(acc[mi][nj], af[mi], bf[nj]);
        }
        __syncthreads();
    }

#pragma unroll
    for (int mi = 0; mi < 4; mi++) {
#pragma unroll
        for (int half = 0; half < 2; half++) {
            const int m = mblk * BM + wm * 64 + mi * 16 + grp + half * 8;
#pragma unroll
            for (int nj = 0; nj < 8; nj++) {
                const int n = nblk * BN + wn * 64 + nj * 8 + 2 * tg;
                float2 v;
                v.x = acc[mi][nj][half * 2 + 0] + bias[n];
                v.y = acc[mi][nj][half * 2 + 1] + bias[n + 1];
                if (MODE == 0) {
                    *(float2*)&out[(size_t)m * D_MODEL + n] = v;
                } else {
                    v.x = rna(v.x * scale);
                    v.y = rna(v.y * scale);
                    const int bb = m >> 11, t = m & (SEQ - 1);
                    const int h = n >> 6, hd = n & (HD - 1);
                    *(float2*)&out[(((size_t)(bb * NHEAD + h)) * SEQ + t) * HD + hd] = v;
                }
            }
        }
    }
}

// ---------------------------------------------------------------------------
// tf32 mma.sync flash attention, cp.async double-buffered K/V.
// Q/K/V: [bh, SEQ, HD], already tf32-rounded (Q also pre-scaled by 0.125).
// CTA: 128 q-rows x 1 bh; 8 warps; warp tile 16 q-rows x 64 keys.
// Q fragments held in registers (loaded once from gmem).
// Smem: Ks[2][64][68] | Vs[2][64][72] | Ps[128][68].
// ---------------------------------------------------------------------------
__global__ void __launch_bounds__(256, 2) attn_kernel(
    const float* __restrict__ Q, const float* __restrict__ K,
    const float* __restrict__ V, float* __restrict__ out)
{
    extern __shared__ __align__(16) float sm[];
    float* Ksb[2] = { sm, sm + KS_TILE };
    float* Vsb[2] = { sm + 2 * KS_TILE, sm + 2 * KS_TILE + VS_TILE };
    float* Ps = sm + 2 * KS_TILE + 2 * VS_TILE;   // [128][68]

    const int tid = threadIdx.x;
    const int w = tid >> 5, lane = tid & 31;
    const int grp = lane >> 2, tg = lane & 3;
    const int bh = blockIdx.y;
    const int q0 = blockIdx.x * AQ;

    const float* Qp = Q + ((size_t)bh * SEQ + q0) * HD;
    const float* Kp = K + (size_t)bh * SEQ * HD;
    const float* Vp = V + (size_t)bh * SEQ * HD;

    const int row0 = w * 16 + grp;            // warp's A-frag rows: row0, row0+8

    // Q fragments -> registers (one-time; Q pre-scaled & pre-rounded)
    uint32_t qa[8][4];
#pragma unroll
    for (int k8 = 0; k8 < 8; k8++) {
        qa[k8][0] = __float_as_uint(Qp[(size_t)row0 * HD + k8 * 8 + tg]);
        qa[k8][1] = __float_as_uint(Qp[(size_t)(row0 + 8) * HD + k8 * 8 + tg]);
        qa[k8][2] = __float_as_uint(Qp[(size_t)row0 * HD + k8 * 8 + tg + 4]);
        qa[k8][3] = __float_as_uint(Qp[(size_t)(row0 + 8) * HD + k8 * 8 + tg + 4]);
    }

    // cp.async issue of one K+V tile (one commit group)
    auto issue = [&](int ti) {
        const int b = ti & 1;
        const float* kq = Kp + (size_t)ti * AK * HD;
        const float* vq = Vp + (size_t)ti * AK * HD;
#pragma unroll
        for (int it = 0; it < 4; it++) {
            const int idx = tid + it * 256;   // 1024 float4 per tensor
            const int r = idx >> 4, c4 = (idx & 15) * 4;
            CP_ASYNC16(s2u(&Ksb[b][r * KS_STRIDE + c4]), &kq[(size_t)r * HD + c4]);
            CP_ASYNC16(s2u(&Vsb[b][r * VS_STRIDE + c4]), &vq[(size_t)r * HD + c4]);
        }
        CP_COMMIT();
    };

    issue(0);
    issue(1);

    float o[8][4];
#pragma unroll
    for (int nj = 0; nj < 8; nj++)
#pragma unroll
        for (int r = 0; r < 4; r++) o[nj][r] = 0.0f;
    float m_lo = -1e30f, m_hi = -1e30f, l_lo = 0.0f, l_hi = 0.0f;

    for (int ti = 0; ti < NT; ti++) {
        const int b = ti & 1;
        if (ti == NT - 1) { CP_WAIT(0); } else { CP_WAIT(1); }
        __syncthreads();

        const float* Ks = Ksb[b];
        const float* Vs = Vsb[b];

        // S = Q * K^T
        float s[8][4];
#pragma unroll
        for (int nj = 0; nj < 8; nj++)
#pragma unroll
            for (int r = 0; r < 4; r++) s[nj][r] = 0.0f;

#pragma unroll
        for (int k8 = 0; k8 < 8; k8++) {
            uint32_t bf[8][2];
#pragma unroll
            for (int nj = 0; nj < 8; nj++) {
                const int n0 = nj * 8 + grp;
                bf[nj][0] = __float_as_uint(Ks[n0 * KS_STRIDE + k8 * 8 + tg]);
                bf[nj][1] = __float_as_uint(Ks[n0 * KS_STRIDE + k8 * 8 + tg + 4]);
            }
#pragma unroll
            for (int nj = 0; nj < 8; nj++)
                mma_tf32(s[nj], qa[k8], bf[nj]);
        }

        // Online softmax (rows grp -> regs 0,1 ; grp+8 -> regs 2,3)
        float mx_lo = -1e30f, mx_hi = -1e30f;
#pragma unroll
        for (int nj = 0; nj < 8; nj++) {
            mx_lo = fmaxf(mx_lo, fmaxf(s[nj][0], s[nj][1]));
            mx_hi = fmaxf(mx_hi, fmaxf(s[nj][2], s[nj][3]));
        }
#pragma unroll
        for (int off = 1; off < 4; off <<= 1) {
            mx_lo = fmaxf(mx_lo, __shfl_xor_sync(0xffffffffu, mx_lo, off));
            mx_hi = fmaxf(mx_hi, __shfl_xor_sync(0xffffffffu, mx_hi, off));
        }
        const float mn_lo = fmaxf(m_lo, mx_lo);
        const float mn_hi = fmaxf(m_hi, mx_hi);
        const float al_lo = __expf(m_lo - mn_lo);
        const float al_hi = __expf(m_hi - mn_hi);

        float rs_lo = 0.0f, rs_hi = 0.0f;
#pragma unroll
        for (int nj = 0; nj < 8; nj++) {
            s[nj][0] = __expf(s[nj][0] - mn_lo);
            s[nj][1] = __expf(s[nj][1] - mn_lo);
            s[nj][2] = __expf(s[nj][2] - mn_hi);
            s[nj][3] = __expf(s[nj][3] - mn_hi);
            rs_lo += s[nj][0] + s[nj][1];
            rs_hi += s[nj][2] + s[nj][3];
        }
#pragma unroll
        for (int off = 1; off < 4; off <<= 1) {
            rs_lo += __shfl_xor_sync(0xffffffffu, rs_lo, off);
            rs_hi += __shfl_xor_sync(0xffffffffu, rs_hi, off);
        }
        l_lo = l_lo * al_lo + rs_lo;
        l_hi = l_hi * al_hi + rs_hi;
        m_lo = mn_lo;
        m_hi = mn_hi;

        // Rescale O; store rounded P (own 16 rows only -> syncwarp suffices)
#pragma unroll
        for (int nj = 0; nj < 8; nj++) {
            o[nj][0] *= al_lo; o[nj][1] *= al_lo;
            o[nj][2] *= al_hi; o[nj][3] *= al_hi;
            float2 plo = { rna(s[nj][0]), rna(s[nj][1]) };
            float2 phi = { rna(s[nj][2]), rna(s[nj][3]) };
            *(float2*)&Ps[row0 * PS_STRIDE + nj * 8 + 2 * tg] = plo;
            *(float2*)&Ps[(row0 + 8) * PS_STRIDE + nj * 8 + 2 * tg] = phi;
        }
        __syncwarp();

        // O += P * V
#pragma unroll
        for (int kk = 0; kk < AK; kk += 8) {
            uint32_t af[4], bf[8][2];
            af[0] = __float_as_uint(Ps[row0 * PS_STRIDE + kk + tg]);
            af[1] = __float_as_uint(Ps[(row0 + 8) * PS_STRIDE + kk + tg]);
            af[2] = __float_as_uint(Ps[row0 * PS_STRIDE + kk + tg + 4]);
            af[3] = __float_as_uint(Ps[(row0 + 8) * PS_STRIDE + kk + tg + 4]);
#pragma unroll
            for (int nj = 0; nj < 8; nj++) {
                const int n0 = nj * 8 + grp;
                bf[nj][0] = __float_as_uint(Vs[(kk + tg) * VS_STRIDE + n0]);
                bf[nj][1] = __float_as_uint(Vs[(kk + tg + 4) * VS_STRIDE + n0]);
            }
#pragma unroll
            for (int nj = 0; nj < 8; nj++)
                mma_tf32(o[nj], af, bf[nj]);
        }
        __syncthreads();          // all warps done reading Ks[b]/Vs[b]

        if (ti + 2 < NT) issue(ti + 2);
    }

    // Normalize, round to tf32, scatter to [4096, 1024]
    const int bb = bh >> 4;
    const int h  = bh & (NHEAD - 1);
    const float inv_lo = 1.0f / l_lo;
    const float inv_hi = 1.0f / l_hi;
    const int grow_lo = bb * SEQ + q0 + row0;
    const int colb = h * HD;
#pragma unroll
    for (int nj = 0; nj < 8; nj++) {
        const int col = colb + nj * 8 + 2 * tg;
        float2 vlo = { rna(o[nj][0] * inv_lo), rna(o[nj][1] * inv_lo) };
        float2 vhi = { rna(o[nj][2] * inv_hi), rna(o[nj][3] * inv_hi) };
        *(float2*)&out[(size_t)grow_lo * D_MODEL + col] = vlo;
        *(float2*)&out[(size_t)(grow_lo + 8) * D_MODEL + col] = vhi;
    }
}

// ---------------------------------------------------------------------------
extern "C" void kernel_launch(void* const* d_in, const int* in_sizes, int n_in,
                              void* d_out, int out_size)
{
    (void)in_sizes; (void)n_in; (void)out_size;
    const float* x  = (const float*)d_in[0];
    const float* Wq = (const float*)d_in[1];
    const float* bq = (const float*)d_in[2];
    const float* Wk = (const float*)d_in[3];
    const float* bk = (const float*)d_in[4];
    const float* Wv = (const float*)d_in[5];
    const float* bv = (const float*)d_in[6];
    const float* Wo = (const float*)d_in[7];
    const float* bo = (const float*)d_in[8];
    float* out = (float*)d_out;

    float *qp, *kp, *vp, *ap, *xc, *wc;
    cudaGetSymbolAddress((void**)&qp, g_Q);
    cudaGetSymbolAddress((void**)&kp, g_K);
    cudaGetSymbolAddress((void**)&vp, g_V);
    cudaGetSymbolAddress((void**)&ap, g_A);
    cudaGetSymbolAddress((void**)&xc, g_Xc);
    cudaGetSymbolAddress((void**)&wc, g_Wc);

    cudaFuncSetAttribute(gemm_tc<0>, cudaFuncAttributeMaxDynamicSharedMemorySize, GEMM_SMEM);
    cudaFuncSetAttribute(gemm_tc<1>, cudaFuncAttributeMaxDynamicSharedMemorySize, GEMM_SMEM);
    cudaFuncSetAttribute(attn_kernel, cudaFuncAttributeMaxDynamicSharedMemorySize, ATTN_SMEM);

    const int NX4 = MTOT * D_MODEL / 4;
    const int NW4 = D_MODEL * D_MODEL / 4;
    const dim3 gridG(D_MODEL / BN, MTOT / BM);   // (8, 32)

    cvt_tf32<<<NX4 / 256, 256>>>((const float4*)x, (float4*)xc, NX4);

    cvt_tf32<<<NW4 / 256, 256>>>((const float4*)Wq, (float4*)wc, NW4);
    gemm_tc<1><<<gridG, 128, GEMM_SMEM>>>(xc, wc, bq, qp, 0.125f);
    cvt_tf32<<<NW4 / 256, 256>>>((const float4*)Wk, (float4*)wc, NW4);
    gemm_tc<1><<<gridG, 128, GEMM_SMEM>>>(xc, wc, bk, kp, 1.0f);
    cvt_tf32<<<NW4 / 256, 256>>>((const float4*)Wv, (float4*)wc, NW4);
    gemm_tc<1><<<gridG, 128, GEMM_SMEM>>>(xc, wc, bv, vp, 1.0f);

    const dim3 gridA(SEQ / AQ, BH);              // (16, 32)
    attn_kernel<<<gridA, 256, ATTN_SMEM>>>(qp, kp, vp, ap);

    cvt_tf32<<<NW4 / 256, 256>>>((const float4*)Wo, (float4*)wc, NW4);
    gemm_tc<0><<<gridG, 128, GEMM_SMEM>>>(ap, wc, bo, out, 1.0f);
}

// round 11
// speedup vs baseline: 1.0137x; 1.0137x over previous
#include <cuda_runtime.h>
#include <cstdint>
#include <math.h>

#define D_MODEL 1024
#define SEQ     2048
#define BATCH   2
#define NHEAD   16
#define HD      64
#define MTOT    (BATCH * SEQ)   // 4096
#define BH      (BATCH * NHEAD) // 32

// ---- GEMM tiling (tf32 mma.sync) ----
#define BM 128
#define BN 128
#define BK 32
#define KI (D_MODEL / BK)        // 32
#define AS_STRIDE 40
#define BS_STRIDE 136
#define AS_FLOATS (BM * AS_STRIDE)
#define BS_FLOATS (BK * BS_STRIDE)
#define STAGE_FLOATS (AS_FLOATS + BS_FLOATS)
#define GEMM_SMEM (2 * STAGE_FLOATS * 4)

// ---- attention tiling ----
#define AQ 128                   // q-rows per CTA
#define AK 32                    // keys per k-tile (reduced: kills reg spills)
#define NT (SEQ / AK)            // 64 tiles
#define KS_STRIDE 68
#define VS_STRIDE 72
#define PS_STRIDE 36
#define KS_TILE (AK * KS_STRIDE)             // 2176 floats
#define VS_TILE (AK * VS_STRIDE)             // 2304 floats
#define ATTN_SMEM ((2 * KS_TILE + 2 * VS_TILE + AQ * PS_STRIDE) * 4) // 54272 B

// ---- scratch ----
__device__ __align__(1024) float g_Q[(size_t)BH * SEQ * HD];
__device__ __align__(1024) float g_K[(size_t)BH * SEQ * HD];
__device__ __align__(1024) float g_V[(size_t)BH * SEQ * HD];
__device__ __align__(1024) float g_A[(size_t)MTOT * D_MODEL];
__device__ __align__(1024) float g_Xc[(size_t)MTOT * D_MODEL];
__device__ __align__(1024) float g_Wc[(size_t)D_MODEL * D_MODEL];

__device__ __forceinline__ uint32_t s2u(const void* p) {
    uint32_t a;
    asm("{ .reg .u64 t; cvta.to.shared.u64 t, %1; cvt.u32.u64 %0, t; }" : "=r"(a) : "l"(p));
    return a;
}
__device__ __forceinline__ float rna(float x) {
    asm("cvt.rna.tf32.f32 %0, %0;" : "+f"(x));
    return x;
}

#define CP_ASYNC16(dst, src) \
    asm volatile("cp.async.ca.shared.global [%0], [%1], 16;" :: "r"(dst), "l"(src) : "memory")
#define CP_COMMIT()  asm volatile("cp.async.commit_group;" ::: "memory")
#define CP_WAIT(N)   asm volatile("cp.async.wait_group %0;" :: "n"(N) : "memory")

__device__ __forceinline__ void mma_tf32(float* d, const uint32_t* a, const uint32_t* b) {
    asm volatile(
        "mma.sync.aligned.m16n8k8.row.col.f32.tf32.tf32.f32 "
        "{%0,%1,%2,%3}, {%4,%5,%6,%7}, {%8,%9}, {%0,%1,%2,%3};"
        : "+f"(d[0]), "+f"(d[1]), "+f"(d[2]), "+f"(d[3])
        : "r"(a[0]), "r"(a[1]), "r"(a[2]), "r"(a[3]), "r"(b[0]), "r"(b[1]));
}

// ---------------------------------------------------------------------------
__global__ void __launch_bounds__(256) cvt_tf32(const float4* __restrict__ src,
                                                float4* __restrict__ dst, int n4)
{
    const int i = blockIdx.x * 256 + threadIdx.x;
    if (i < n4) {
        float4 v = src[i];
        v.x = rna(v.x); v.y = rna(v.y); v.z = rna(v.z); v.w = rna(v.w);
        dst[i] = v;
    }
}

// ---------------------------------------------------------------------------
// tf32 mma.sync GEMM. MODE 0: row-major out (plain fp32).
// MODE 1: scatter to [bh, t, hd] with rna((acc + bias) * scale).
// ---------------------------------------------------------------------------
template <int MODE>
__global__ void __launch_bounds__(128) gemm_tc(
    const float* __restrict__ A, const float* __restrict__ W,
    const float* __restrict__ bias, float* __restrict__ out, float scale)
{
    extern __shared__ __align__(16) float smem[];
    float* As[2] = { smem, smem + STAGE_FLOATS };
    float* Bs[2] = { smem + AS_FLOATS, smem + STAGE_FLOATS + AS_FLOATS };

    const int tid = threadIdx.x;
    const int wid = tid >> 5, lane = tid & 31;
    const int wm = wid >> 1, wn = wid & 1;
    const int grp = lane >> 2, tg = lane & 3;
    const int nblk = blockIdx.x, mblk = blockIdx.y;

    const float* Ag = A + (size_t)mblk * BM * D_MODEL;
    const float* Wg = W + nblk * BN;

    auto load_stage = [&](int s, int k0) {
        float* as = As[s];
        float* bs = Bs[s];
#pragma unroll
        for (int j = 0; j < 8; j++) {
            const int c = tid + j * 128;
            const int r = c >> 3, q = c & 7;
            CP_ASYNC16(s2u(&as[r * AS_STRIDE + q * 4]),
                       &Ag[(size_t)r * D_MODEL + k0 + q * 4]);
        }
#pragma unroll
        for (int j = 0; j < 8; j++) {
            const int c = tid + j * 128;
            const int r = c >> 5, q = c & 31;
            CP_ASYNC16(s2u(&bs[r * BS_STRIDE + q * 4]),
                       &Wg[(size_t)(k0 + r) * D_MODEL + q * 4]);
        }
        CP_COMMIT();
    };

    float acc[4][8][4];
#pragma unroll
    for (int i = 0; i < 4; i++)
#pragma unroll
        for (int j = 0; j < 8; j++)
#pragma unroll
            for (int r = 0; r < 4; r++) acc[i][j][r] = 0.0f;

    load_stage(0, 0);

    for (int kt = 0; kt < KI; kt++) {
        if (kt + 1 < KI) {
            load_stage((kt + 1) & 1, (kt + 1) * BK);
            CP_WAIT(1);
        } else {
            CP_WAIT(0);
        }
        __syncthreads();

        const float* as = As[kt & 1];
        const float* bs = Bs[kt & 1];
#pragma unroll
        for (int kk = 0; kk < BK; kk += 8) {
            uint32_t af[4][4], bf[8][2];
#pragma unroll
            for (int mi = 0; mi < 4; mi++) {
                const int r0 = wm * 64 + mi * 16 + grp;
                af[mi][0] = __float_as_uint(as[r0 * AS_STRIDE + kk + tg]);
                af[mi][1] = __float_as_uint(as[(r0 + 8) * AS_STRIDE + kk + tg]);
                af[mi][2] = __float_as_uint(as[r0 * AS_STRIDE + kk + tg + 4]);
                af[mi][3] = __float_as_uint(as[(r0 + 8) * AS_STRIDE + kk + tg + 4]);
            }
#pragma unroll
            for (int nj = 0; nj < 8; nj++) {
                const int n0 = wn * 64 + nj * 8 + grp;
                bf[nj][0] = __float_as_uint(bs[(kk + tg) * BS_STRIDE + n0]);
                bf[nj][1] = __float_as_uint(bs[(kk + tg + 4) * BS_STRIDE + n0]);
            }
#pragma unroll
            for (int mi = 0; mi < 4; mi++)
#pragma unroll
                for (int nj = 0; nj < 8; nj++)
                    mma_tf32(acc[mi][nj], af[mi], bf[nj]);
        }
        __syncthreads();
    }

#pragma unroll
    for (int mi = 0; mi < 4; mi++) {
#pragma unroll
        for (int half = 0; half < 2; half++) {
            const int m = mblk * BM + wm * 64 + mi * 16 + grp + half * 8;
#pragma unroll
            for (int nj = 0; nj < 8; nj++) {
                const int n = nblk * BN + wn * 64 + nj * 8 + 2 * tg;
                float2 v;
                v.x = acc[mi][nj][half * 2 + 0] + bias[n];
                v.y = acc[mi][nj][half * 2 + 1] + bias[n + 1];
                if (MODE == 0) {
                    *(float2*)&out[(size_t)m * D_MODEL + n] = v;
                } else {
                    v.x = rna(v.x * scale);
                    v.y = rna(v.y * scale);
                    const int bb = m >> 11, t = m & (SEQ - 1);
                    const int h = n >> 6, hd = n & (HD - 1);
                    *(float2*)&out[(((size_t)(bb * NHEAD + h)) * SEQ + t) * HD + hd] = v;
                }
            }
        }
    }
}

// ---------------------------------------------------------------------------
// tf32 mma.sync flash attention, cp.async double-buffered K/V, AK=32.
// Q/K/V: [bh, SEQ, HD], already tf32-rounded (Q also pre-scaled by 0.125).
// CTA: 128 q-rows x 1 bh; 8 warps; warp tile 16 q-rows x 32 keys per k-tile.
// Q fragments in registers (32); peak regs ~105 -> no spills at 2 CTAs/SM.
// Smem: Ks[2][32][68] | Vs[2][32][72] | Ps[128][36]  (54272 B).
// ---------------------------------------------------------------------------
__global__ void __launch_bounds__(256, 2) attn_kernel(
    const float* __restrict__ Q, const float* __restrict__ K,
    const float* __restrict__ V, float* __restrict__ out)
{
    extern __shared__ __align__(16) float sm[];
    float* Ksb[2] = { sm, sm + KS_TILE };
    float* Vsb[2] = { sm + 2 * KS_TILE, sm + 2 * KS_TILE + VS_TILE };
    float* Ps = sm + 2 * KS_TILE + 2 * VS_TILE;   // [128][36]

    const int tid = threadIdx.x;
    const int w = tid >> 5, lane = tid & 31;
    const int grp = lane >> 2, tg = lane & 3;
    const int bh = blockIdx.y;
    const int q0 = blockIdx.x * AQ;

    const float* Qp = Q + ((size_t)bh * SEQ + q0) * HD;
    const float* Kp = K + (size_t)bh * SEQ * HD;
    const float* Vp = V + (size_t)bh * SEQ * HD;

    const int row0 = w * 16 + grp;            // warp's A-frag rows: row0, row0+8

    // Q fragments -> registers (one-time; Q pre-scaled & pre-rounded)
    uint32_t qa[8][4];
#pragma unroll
    for (int k8 = 0; k8 < 8; k8++) {
        qa[k8][0] = __float_as_uint(Qp[(size_t)row0 * HD + k8 * 8 + tg]);
        qa[k8][1] = __float_as_uint(Qp[(size_t)(row0 + 8) * HD + k8 * 8 + tg]);
        qa[k8][2] = __float_as_uint(Qp[(size_t)row0 * HD + k8 * 8 + tg + 4]);
        qa[k8][3] = __float_as_uint(Qp[(size_t)(row0 + 8) * HD + k8 * 8 + tg + 4]);
    }

    // cp.async issue of one K+V tile (one commit group): 32 rows x 64 floats each
    auto issue = [&](int ti) {
        const int b = ti & 1;
        const float* kq = Kp + (size_t)ti * AK * HD;
        const float* vq = Vp + (size_t)ti * AK * HD;
#pragma unroll
        for (int it = 0; it < 2; it++) {
            const int idx = tid + it * 256;   // 512 float4 per tensor
            const int r = idx >> 4, c4 = (idx & 15) * 4;
            CP_ASYNC16(s2u(&Ksb[b][r * KS_STRIDE + c4]), &kq[(size_t)r * HD + c4]);
            CP_ASYNC16(s2u(&Vsb[b][r * VS_STRIDE + c4]), &vq[(size_t)r * HD + c4]);
        }
        CP_COMMIT();
    };

    issue(0);
    issue(1);

    float o[8][4];
#pragma unroll
    for (int nj = 0; nj < 8; nj++)
#pragma unroll
        for (int r = 0; r < 4; r++) o[nj][r] = 0.0f;
    float m_lo = -1e30f, m_hi = -1e30f, l_lo = 0.0f, l_hi = 0.0f;

    for (int ti = 0; ti < NT; ti++) {
        const int b = ti & 1;
        if (ti == NT - 1) { CP_WAIT(0); } else { CP_WAIT(1); }
        __syncthreads();

        const float* Ks = Ksb[b];
        const float* Vs = Vsb[b];

        // S = Q * K^T  (16 rows x 32 keys)
        float s[4][4];
#pragma unroll
        for (int nj = 0; nj < 4; nj++)
#pragma unroll
            for (int r = 0; r < 4; r++) s[nj][r] = 0.0f;

#pragma unroll
        for (int k8 = 0; k8 < 8; k8++) {
            uint32_t bf[4][2];
#pragma unroll
            for (int nj = 0; nj < 4; nj++) {
                const int n0 = nj * 8 + grp;
                bf[nj][0] = __float_as_uint(Ks[n0 * KS_STRIDE + k8 * 8 + tg]);
                bf[nj][1] = __float_as_uint(Ks[n0 * KS_STRIDE + k8 * 8 + tg + 4]);
            }
#pragma unroll
            for (int nj = 0; nj < 4; nj++)
                mma_tf32(s[nj], qa[k8], bf[nj]);
        }

        // Online softmax (rows grp -> regs 0,1 ; grp+8 -> regs 2,3)
        float mx_lo = -1e30f, mx_hi = -1e30f;
#pragma unroll
        for (int nj = 0; nj < 4; nj++) {
            mx_lo = fmaxf(mx_lo, fmaxf(s[nj][0], s[nj][1]));
            mx_hi = fmaxf(mx_hi, fmaxf(s[nj][2], s[nj][3]));
        }
#pragma unroll
        for (int off = 1; off < 4; off <<= 1) {
            mx_lo = fmaxf(mx_lo, __shfl_xor_sync(0xffffffffu, mx_lo, off));
            mx_hi = fmaxf(mx_hi, __shfl_xor_sync(0xffffffffu, mx_hi, off));
        }
        const float mn_lo = fmaxf(m_lo, mx_lo);
        const float mn_hi = fmaxf(m_hi, mx_hi);
        const float al_lo = __expf(m_lo - mn_lo);
        const float al_hi = __expf(m_hi - mn_hi);

        float rs_lo = 0.0f, rs_hi = 0.0f;
#pragma unroll
        for (int nj = 0; nj < 4; nj++) {
            s[nj][0] = __expf(s[nj][0] - mn_lo);
            s[nj][1] = __expf(s[nj][1] - mn_lo);
            s[nj][2] = __expf(s[nj][2] - mn_hi);
            s[nj][3] = __expf(s[nj][3] - mn_hi);
            rs_lo += s[nj][0] + s[nj][1];
            rs_hi += s[nj][2] + s[nj][3];
        }
#pragma unroll
        for (int off = 1; off < 4; off <<= 1) {
            rs_lo += __shfl_xor_sync(0xffffffffu, rs_lo, off);
            rs_hi += __shfl_xor_sync(0xffffffffu, rs_hi, off);
        }
        l_lo = l_lo * al_lo + rs_lo;
        l_hi = l_hi * al_hi + rs_hi;
        m_lo = mn_lo;
        m_hi = mn_hi;

        // Rescale O; store rounded P (own 16 rows only -> syncwarp suffices)
#pragma unroll
        for (int nj = 0; nj < 8; nj++) {
            o[nj][0] *= al_lo; o[nj][1] *= al_lo;
            o[nj][2] *= al_hi; o[nj][3] *= al_hi;
        }
#pragma unroll
        for (int nj = 0; nj < 4; nj++) {
            float2 plo = { rna(s[nj][0]), rna(s[nj][1]) };
            float2 phi = { rna(s[nj][2]), rna(s[nj][3]) };
            *(float2*)&Ps[row0 * PS_STRIDE + nj * 8 + 2 * tg] = plo;
            *(float2*)&Ps[(row0 + 8) * PS_STRIDE + nj * 8 + 2 * tg] = phi;
        }
        __syncwarp();

        // O += P * V  (P: 16 x 32, V: 32 x 64)
#pragma unroll
        for (int kk = 0; kk < AK; kk += 8) {
            uint32_t af[4], bf[8][2];
            af[0] = __float_as_uint(Ps[row0 * PS_STRIDE + kk + tg]);
            af[1] = __float_as_uint(Ps[(row0 + 8) * PS_STRIDE + kk + tg]);
            af[2] = __float_as_uint(Ps[row0 * PS_STRIDE + kk + tg + 4]);
            af[3] = __float_as_uint(Ps[(row0 + 8) * PS_STRIDE + kk + tg + 4]);
#pragma unroll
            for (int nj = 0; nj < 8; nj++) {
                const int n0 = nj * 8 + grp;
                bf[nj][0] = __float_as_uint(Vs[(kk + tg) * VS_STRIDE + n0]);
                bf[nj][1] = __float_as_uint(Vs[(kk + tg + 4) * VS_STRIDE + n0]);
            }
#pragma unroll
            for (int nj = 0; nj < 8; nj++)
                mma_tf32(o[nj], af, bf[nj]);
        }
        __syncthreads();          // all warps done reading Ks[b]/Vs[b]

        if (ti + 2 < NT) issue(ti + 2);
    }

    // Normalize, round to tf32, scatter to [4096, 1024]
    const int bb = bh >> 4;
    const int h  = bh & (NHEAD - 1);
    const float inv_lo = 1.0f / l_lo;
    const float inv_hi = 1.0f / l_hi;
    const int grow_lo = bb * SEQ + q0 + row0;
    const int colb = h * HD;
#pragma unroll
    for (int nj = 0; nj < 8; nj++) {
        const int col = colb + nj * 8 + 2 * tg;
        float2 vlo = { rna(o[nj][0] * inv_lo), rna(o[nj][1] * inv_lo) };
        float2 vhi = { rna(o[nj][2] * inv_hi), rna(o[nj][3] * inv_hi) };
        *(float2*)&out[(size_t)grow_lo * D_MODEL + col] = vlo;
        *(float2*)&out[(size_t)(grow_lo + 8) * D_MODEL + col] = vhi;
    }
}

// ---------------------------------------------------------------------------
extern "C" void kernel_launch(void* const* d_in, const int* in_sizes, int n_in,
                              void* d_out, int out_size)
{
    (void)in_sizes; (void)n_in; (void)out_size;
    const float* x  = (const float*)d_in[0];
    const float* Wq = (const float*)d_in[1];
    const float* bq = (const float*)d_in[2];
    const float* Wk = (const float*)d_in[3];
    const float* bk = (const float*)d_in[4];
    const float* Wv = (const float*)d_in[5];
    const float* bv = (const float*)d_in[6];
    const float* Wo = (const float*)d_in[7];
    const float* bo = (const float*)d_in[8];
    float* out = (float*)d_out;

    float *qp, *kp, *vp, *ap, *xc, *wc;
    cudaGetSymbolAddress((void**)&qp, g_Q);
    cudaGetSymbolAddress((void**)&kp, g_K);
    cudaGetSymbolAddress((void**)&vp, g_V);
    cudaGetSymbolAddress((void**)&ap, g_A);
    cudaGetSymbolAddress((void**)&xc, g_Xc);
    cudaGetSymbolAddress((void**)&wc, g_Wc);

    cudaFuncSetAttribute(gemm_tc<0>, cudaFuncAttributeMaxDynamicSharedMemorySize, GEMM_SMEM);
    cudaFuncSetAttribute(gemm_tc<1>, cudaFuncAttributeMaxDynamicSharedMemorySize, GEMM_SMEM);
    cudaFuncSetAttribute(attn_kernel, cudaFuncAttributeMaxDynamicSharedMemorySize, ATTN_SMEM);

    const int NX4 = MTOT * D_MODEL / 4;
    const int NW4 = D_MODEL * D_MODEL / 4;
    const dim3 gridG(D_MODEL / BN, MTOT / BM);   // (8, 32)

    cvt_tf32<<<NX4 / 256, 256>>>((const float4*)x, (float4*)xc, NX4);

    cvt_tf32<<<NW4 / 256, 256>>>((const float4*)Wq, (float4*)wc, NW4);
    gemm_tc<1><<<gridG, 128, GEMM_SMEM>>>(xc, wc, bq, qp, 0.125f);
    cvt_tf32<<<NW4 / 256, 256>>>((const float4*)Wk, (float4*)wc, NW4);
    gemm_tc<1><<<gridG, 128, GEMM_SMEM>>>(xc, wc, bk, kp, 1.0f);
    cvt_tf32<<<NW4 / 256, 256>>>((const float4*)Wv, (float4*)wc, NW4);
    gemm_tc<1><<<gridG, 128, GEMM_SMEM>>>(xc, wc, bv, vp, 1.0f);

    const dim3 gridA(SEQ / AQ, BH);              // (16, 32)
    attn_kernel<<<gridA, 256, ATTN_SMEM>>>(qp, kp, vp, ap);

    cvt_tf32<<<NW4 / 256, 256>>>((const float4*)Wo, (float4*)wc, NW4);
    gemm_tc<0><<<gridG, 128, GEMM_SMEM>>>(ap, wc, bo, out, 1.0f);
}

// round 12
// speedup vs baseline: 1.0781x; 1.0635x over previous
#include <cuda_runtime.h>
#include <cstdint>
#include <math.h>

#define D_MODEL 1024
#define SEQ     2048
#define BATCH   2
#define NHEAD   16
#define HD      64
#define MTOT    (BATCH * SEQ)   // 4096
#define BH      (BATCH * NHEAD) // 32

// ---- GEMM tiling (tf32 mma.sync) ----
#define BM 128
#define BN 128
#define BK 32
#define KI (D_MODEL / BK)        // 32
#define AS_STRIDE 40
#define BS_STRIDE 136
#define AS_FLOATS (BM * AS_STRIDE)
#define BS_FLOATS (BK * BS_STRIDE)
#define STAGE_FLOATS (AS_FLOATS + BS_FLOATS)
#define GEMM_SMEM (2 * STAGE_FLOATS * 4)

// ---- attention tiling (R5 structure) ----
#define AQ 128                   // q-rows per CTA
#define AK 64                    // keys per k-tile
#define QS_STRIDE 68
#define PS_STRIDE 68             // P / K union region
#define VS_STRIDE 72
#define ATTN_SMEM ((AQ * QS_STRIDE + AQ * PS_STRIDE + AK * VS_STRIDE) * 4) // 88064

// ---- scratch ----
__device__ __align__(1024) float g_Q[(size_t)BH * SEQ * HD];
__device__ __align__(1024) float g_K[(size_t)BH * SEQ * HD];
__device__ __align__(1024) float g_V[(size_t)BH * SEQ * HD];
__device__ __align__(1024) float g_A[(size_t)MTOT * D_MODEL];
__device__ __align__(1024) float g_Xc[(size_t)MTOT * D_MODEL];
__device__ __align__(1024) float g_Wc[(size_t)D_MODEL * D_MODEL];

__device__ __forceinline__ uint32_t s2u(const void* p) {
    uint32_t a;
    asm("{ .reg .u64 t; cvta.to.shared.u64 t, %1; cvt.u32.u64 %0, t; }" : "=r"(a) : "l"(p));
    return a;
}
__device__ __forceinline__ float rna(float x) {
    asm("cvt.rna.tf32.f32 %0, %0;" : "+f"(x));
    return x;
}

#define CP_ASYNC16(dst, src) \
    asm volatile("cp.async.ca.shared.global [%0], [%1], 16;" :: "r"(dst), "l"(src) : "memory")
#define CP_COMMIT()  asm volatile("cp.async.commit_group;" ::: "memory")
#define CP_WAIT(N)   asm volatile("cp.async.wait_group %0;" :: "n"(N) : "memory")

__device__ __forceinline__ void mma_tf32(float* d, const uint32_t* a, const uint32_t* b) {
    asm volatile(
        "mma.sync.aligned.m16n8k8.row.col.f32.tf32.tf32.f32 "
        "{%0,%1,%2,%3}, {%4,%5,%6,%7}, {%8,%9}, {%0,%1,%2,%3};"
        : "+f"(d[0]), "+f"(d[1]), "+f"(d[2]), "+f"(d[3])
        : "r"(a[0]), "r"(a[1]), "r"(a[2]), "r"(a[3]), "r"(b[0]), "r"(b[1]));
}

// ---------------------------------------------------------------------------
__global__ void __launch_bounds__(256) cvt_tf32(const float4* __restrict__ src,
                                                float4* __restrict__ dst, int n4)
{
    const int i = blockIdx.x * 256 + threadIdx.x;
    if (i < n4) {
        float4 v = src[i];
        v.x = rna(v.x); v.y = rna(v.y); v.z = rna(v.z); v.w = rna(v.w);
        dst[i] = v;
    }
}

// ---------------------------------------------------------------------------
// tf32 mma.sync GEMM. MODE 0: row-major out (plain fp32).
// MODE 1: scatter to [bh, t, hd] with rna((acc + bias) * scale).
// ---------------------------------------------------------------------------
template <int MODE>
__global__ void __launch_bounds__(128) gemm_tc(
    const float* __restrict__ A, const float* __restrict__ W,
    const float* __restrict__ bias, float* __restrict__ out, float scale)
{
    extern __shared__ __align__(16) float smem[];
    float* As[2] = { smem, smem + STAGE_FLOATS };
    float* Bs[2] = { smem + AS_FLOATS, smem + STAGE_FLOATS + AS_FLOATS };

    const int tid = threadIdx.x;
    const int wid = tid >> 5, lane = tid & 31;
    const int wm = wid >> 1, wn = wid & 1;
    const int grp = lane >> 2, tg = lane & 3;
    const int nblk = blockIdx.x, mblk = blockIdx.y;

    const float* Ag = A + (size_t)mblk * BM * D_MODEL;
    const float* Wg = W + nblk * BN;

    auto load_stage = [&](int s, int k0) {
        float* as = As[s];
        float* bs = Bs[s];
#pragma unroll
        for (int j = 0; j < 8; j++) {
            const int c = tid + j * 128;
            const int r = c >> 3, q = c & 7;
            CP_ASYNC16(s2u(&as[r * AS_STRIDE + q * 4]),
                       &Ag[(size_t)r * D_MODEL + k0 + q * 4]);
        }
#pragma unroll
        for (int j = 0; j < 8; j++) {
            const int c = tid + j * 128;
            const int r = c >> 5, q = c & 31;
            CP_ASYNC16(s2u(&bs[r * BS_STRIDE + q * 4]),
                       &Wg[(size_t)(k0 + r) * D_MODEL + q * 4]);
        }
        CP_COMMIT();
    };

    float acc[4][8][4];
#pragma unroll
    for (int i = 0; i < 4; i++)
#pragma unroll
        for (int j = 0; j < 8; j++)
#pragma unroll
            for (int r = 0; r < 4; r++) acc[i][j][r] = 0.0f;

    load_stage(0, 0);

    for (int kt = 0; kt < KI; kt++) {
        if (kt + 1 < KI) {
            load_stage((kt + 1) & 1, (kt + 1) * BK);
            CP_WAIT(1);
        } else {
            CP_WAIT(0);
        }
        __syncthreads();

        const float* as = As[kt & 1];
        const float* bs = Bs[kt & 1];
#pragma unroll
        for (int kk = 0; kk < BK; kk += 8) {
            uint32_t af[4][4], bf[8][2];
#pragma unroll
            for (int mi = 0; mi < 4; mi++) {
                const int r0 = wm * 64 + mi * 16 + grp;
                af[mi][0] = __float_as_uint(as[r0 * AS_STRIDE + kk + tg]);
                af[mi][1] = __float_as_uint(as[(r0 + 8) * AS_STRIDE + kk + tg]);
                af[mi][2] = __float_as_uint(as[r0 * AS_STRIDE + kk + tg + 4]);
                af[mi][3] = __float_as_uint(as[(r0 + 8) * AS_STRIDE + kk + tg + 4]);
            }
#pragma unroll
            for (int nj = 0; nj < 8; nj++) {
                const int n0 = wn * 64 + nj * 8 + grp;
                bf[nj][0] = __float_as_uint(bs[(kk + tg) * BS_STRIDE + n0]);
                bf[nj][1] = __float_as_uint(bs[(kk + tg + 4) * BS_STRIDE + n0]);
            }
#pragma unroll
            for (int mi = 0; mi < 4; mi++)
#pragma unroll
                for (int nj = 0; nj < 8; nj++)
                    mma_tf32(acc[mi][nj], af[mi], bf[nj]);
        }
        __syncthreads();
    }

#pragma unroll
    for (int mi = 0; mi < 4; mi++) {
#pragma unroll
        for (int half = 0; half < 2; half++) {
            const int m = mblk * BM + wm * 64 + mi * 16 + grp + half * 8;
#pragma unroll
            for (int nj = 0; nj < 8; nj++) {
                const int n = nblk * BN + wn * 64 + nj * 8 + 2 * tg;
                float2 v;
                v.x = acc[mi][nj][half * 2 + 0] + bias[n];
                v.y = acc[mi][nj][half * 2 + 1] + bias[n + 1];
                if (MODE == 0) {
                    *(float2*)&out[(size_t)m * D_MODEL + n] = v;
                } else {
                    v.x = rna(v.x * scale);
                    v.y = rna(v.y * scale);
                    const int bb = m >> 11, t = m & (SEQ - 1);
                    const int h = n >> 6, hd = n & (HD - 1);
                    *(float2*)&out[(((size_t)(bb * NHEAD + h)) * SEQ + t) * HD + hd] = v;
                }
            }
        }
    }
}

// ---------------------------------------------------------------------------
// tf32 mma.sync flash attention — R5 structure (proven fastest), with all
// staging rna removed (inputs pre-rounded/pre-scaled by the projection GEMMs).
// Q/K/V: [bh, SEQ, HD]. CTA: 128 q-rows x 1 bh; 8 warps; warp tile 16x64.
// Smem: Qs[128][68] | Ps[128][68] (rows 0..63 double as Ks) | Vs[64][72].
// ---------------------------------------------------------------------------
__global__ void __launch_bounds__(256, 2) attn_kernel(
    const float* __restrict__ Q, const float* __restrict__ K,
    const float* __restrict__ V, float* __restrict__ out)
{
    extern __shared__ __align__(16) float sm[];
    float* Qs = sm;                         // [128][68]
    float* Ps = sm + AQ * QS_STRIDE;        // [128][68]; Ks = rows 0..63
    float* Vs = Ps + AQ * PS_STRIDE;        // [64][72]

    const int tid = threadIdx.x;
    const int w = tid >> 5, lane = tid & 31;
    const int grp = lane >> 2, tg = lane & 3;
    const int bh = blockIdx.y;
    const int q0 = blockIdx.x * AQ;

    const float* Qp = Q + ((size_t)bh * SEQ + q0) * HD;
    const float* Kp = K + (size_t)bh * SEQ * HD;
    const float* Vp = V + (size_t)bh * SEQ * HD;

    // Load Q tile (pure copy: Q already scaled by 0.125 and tf32-rounded)
#pragma unroll
    for (int it = 0; it < 8; it++) {
        const int idx = tid + it * 256;       // 2048 float4
        const int r = idx >> 4, c4 = (idx & 15) * 4;
        *(float4*)&Qs[r * QS_STRIDE + c4] = *(const float4*)&Qp[(size_t)r * HD + c4];
    }

    float o[8][4];
#pragma unroll
    for (int nj = 0; nj < 8; nj++)
#pragma unroll
        for (int r = 0; r < 4; r++) o[nj][r] = 0.0f;
    float m_lo = -1e30f, m_hi = -1e30f, l_lo = 0.0f, l_hi = 0.0f;

    const int row0 = w * 16 + grp;           // warp's A-frag rows: row0, row0+8

    for (int kt = 0; kt < SEQ; kt += AK) {
        // Load K tile -> Ps rows 0..63, V tile -> Vs (pure copies, pre-rounded)
#pragma unroll
        for (int it = 0; it < 4; it++) {
            const int idx = tid + it * 256;   // 1024 float4
            const int r = idx >> 4, c4 = (idx & 15) * 4;
            *(float4*)&Ps[r * PS_STRIDE + c4] = *(const float4*)&Kp[(size_t)(kt + r) * HD + c4];
            *(float4*)&Vs[r * VS_STRIDE + c4] = *(const float4*)&Vp[(size_t)(kt + r) * HD + c4];
        }
        __syncthreads();

        // S = Q * K^T  (warp: 16 rows x 64 keys)
        float s[8][4];
#pragma unroll
        for (int nj = 0; nj < 8; nj++)
#pragma unroll
            for (int r = 0; r < 4; r++) s[nj][r] = 0.0f;

#pragma unroll
        for (int kk = 0; kk < HD; kk += 8) {
            uint32_t af[4], bf[8][2];
            af[0] = __float_as_uint(Qs[row0 * QS_STRIDE + kk + tg]);
            af[1] = __float_as_uint(Qs[(row0 + 8) * QS_STRIDE + kk + tg]);
            af[2] = __float_as_uint(Qs[row0 * QS_STRIDE + kk + tg + 4]);
            af[3] = __float_as_uint(Qs[(row0 + 8) * QS_STRIDE + kk + tg + 4]);
#pragma unroll
            for (int nj = 0; nj < 8; nj++) {
                const int n0 = nj * 8 + grp;
                bf[nj][0] = __float_as_uint(Ps[n0 * PS_STRIDE + kk + tg]);
                bf[nj][1] = __float_as_uint(Ps[n0 * PS_STRIDE + kk + tg + 4]);
            }
#pragma unroll
            for (int nj = 0; nj < 8; nj++)
                mma_tf32(s[nj], af, bf[nj]);
        }
        __syncthreads();   // all Ks reads complete before P overwrites rows 0..63

        // Online softmax (rows grp -> regs 0,1 ; grp+8 -> regs 2,3)
        float mx_lo = -1e30f, mx_hi = -1e30f;
#pragma unroll
        for (int nj = 0; nj < 8; nj++) {
            mx_lo = fmaxf(mx_lo, fmaxf(s[nj][0], s[nj][1]));
            mx_hi = fmaxf(mx_hi, fmaxf(s[nj][2], s[nj][3]));
        }
#pragma unroll
        for (int off = 1; off < 4; off <<= 1) {
            mx_lo = fmaxf(mx_lo, __shfl_xor_sync(0xffffffffu, mx_lo, off));
            mx_hi = fmaxf(mx_hi, __shfl_xor_sync(0xffffffffu, mx_hi, off));
        }
        const float mn_lo = fmaxf(m_lo, mx_lo);
        const float mn_hi = fmaxf(m_hi, mx_hi);
        const float al_lo = __expf(m_lo - mn_lo);
        const float al_hi = __expf(m_hi - mn_hi);

        float rs_lo = 0.0f, rs_hi = 0.0f;
#pragma unroll
        for (int nj = 0; nj < 8; nj++) {
            s[nj][0] = __expf(s[nj][0] - mn_lo);
            s[nj][1] = __expf(s[nj][1] - mn_lo);
            s[nj][2] = __expf(s[nj][2] - mn_hi);
            s[nj][3] = __expf(s[nj][3] - mn_hi);
            rs_lo += s[nj][0] + s[nj][1];
            rs_hi += s[nj][2] + s[nj][3];
        }
#pragma unroll
        for (int off = 1; off < 4; off <<= 1) {
            rs_lo += __shfl_xor_sync(0xffffffffu, rs_lo, off);
            rs_hi += __shfl_xor_sync(0xffffffffu, rs_hi, off);
        }
        l_lo = l_lo * al_lo + rs_lo;
        l_hi = l_hi * al_hi + rs_hi;
        m_lo = mn_lo;
        m_hi = mn_hi;

        // Rescale O, store rounded P to smem (own 16 rows only)
#pragma unroll
        for (int nj = 0; nj < 8; nj++) {
            o[nj][0] *= al_lo; o[nj][1] *= al_lo;
            o[nj][2] *= al_hi; o[nj][3] *= al_hi;
            float2 plo = { rna(s[nj][0]), rna(s[nj][1]) };
            float2 phi = { rna(s[nj][2]), rna(s[nj][3]) };
            *(float2*)&Ps[row0 * PS_STRIDE + nj * 8 + 2 * tg] = plo;
            *(float2*)&Ps[(row0 + 8) * PS_STRIDE + nj * 8 + 2 * tg] = phi;
        }
        __syncwarp();

        // O += P * V
#pragma unroll
        for (int kk = 0; kk < AK; kk += 8) {
            uint32_t af[4], bf[8][2];
            af[0] = __float_as_uint(Ps[row0 * PS_STRIDE + kk + tg]);
            af[1] = __float_as_uint(Ps[(row0 + 8) * PS_STRIDE + kk + tg]);
            af[2] = __float_as_uint(Ps[row0 * PS_STRIDE + kk + tg + 4]);
            af[3] = __float_as_uint(Ps[(row0 + 8) * PS_STRIDE + kk + tg + 4]);
#pragma unroll
            for (int nj = 0; nj < 8; nj++) {
                const int n0 = nj * 8 + grp;
                bf[nj][0] = __float_as_uint(Vs[(kk + tg) * VS_STRIDE + n0]);
                bf[nj][1] = __float_as_uint(Vs[(kk + tg + 4) * VS_STRIDE + n0]);
            }
#pragma unroll
            for (int nj = 0; nj < 8; nj++)
                mma_tf32(o[nj], af, bf[nj]);
        }
        __syncthreads();   // P reads done before next K load overwrites
    }

    // Normalize, round to tf32, scatter to [4096, 1024]
    const int bb = bh >> 4;
    const int h  = bh & (NHEAD - 1);
    const float inv_lo = 1.0f / l_lo;
    const float inv_hi = 1.0f / l_hi;
    const int grow_lo = bb * SEQ + q0 + row0;
    const int colb = h * HD;
#pragma unroll
    for (int nj = 0; nj < 8; nj++) {
        const int col = colb + nj * 8 + 2 * tg;
        float2 vlo = { rna(o[nj][0] * inv_lo), rna(o[nj][1] * inv_lo) };
        float2 vhi = { rna(o[nj][2] * inv_hi), rna(o[nj][3] * inv_hi) };
        *(float2*)&out[(size_t)grow_lo * D_MODEL + col] = vlo;
        *(float2*)&out[(size_t)(grow_lo + 8) * D_MODEL + col] = vhi;
    }
}

// ---------------------------------------------------------------------------
extern "C" void kernel_launch(void* const* d_in, const int* in_sizes, int n_in,
                              void* d_out, int out_size)
{
    (void)in_sizes; (void)n_in; (void)out_size;
    const float* x  = (const float*)d_in[0];
    const float* Wq = (const float*)d_in[1];
    const float* bq = (const float*)d_in[2];
    const float* Wk = (const float*)d_in[3];
    const float* bk = (const float*)d_in[4];
    const float* Wv = (const float*)d_in[5];
    const float* bv = (const float*)d_in[6];
    const float* Wo = (const float*)d_in[7];
    const float* bo = (const float*)d_in[8];
    float* out = (float*)d_out;

    float *qp, *kp, *vp, *ap, *xc, *wc;
    cudaGetSymbolAddress((void**)&qp, g_Q);
    cudaGetSymbolAddress((void**)&kp, g_K);
    cudaGetSymbolAddress((void**)&vp, g_V);
    cudaGetSymbolAddress((void**)&ap, g_A);
    cudaGetSymbolAddress((void**)&xc, g_Xc);
    cudaGetSymbolAddress((void**)&wc, g_Wc);

    cudaFuncSetAttribute(gemm_tc<0>, cudaFuncAttributeMaxDynamicSharedMemorySize, GEMM_SMEM);
    cudaFuncSetAttribute(gemm_tc<1>, cudaFuncAttributeMaxDynamicSharedMemorySize, GEMM_SMEM);
    cudaFuncSetAttribute(attn_kernel, cudaFuncAttributeMaxDynamicSharedMemorySize, ATTN_SMEM);

    const int NX4 = MTOT * D_MODEL / 4;
    const int NW4 = D_MODEL * D_MODEL / 4;
    const dim3 gridG(D_MODEL / BN, MTOT / BM);   // (8, 32)

    cvt_tf32<<<NX4 / 256, 256>>>((const float4*)x, (float4*)xc, NX4);

    cvt_tf32<<<NW4 / 256, 256>>>((const float4*)Wq, (float4*)wc, NW4);
    gemm_tc<1><<<gridG, 128, GEMM_SMEM>>>(xc, wc, bq, qp, 0.125f);
    cvt_tf32<<<NW4 / 256, 256>>>((const float4*)Wk, (float4*)wc, NW4);
    gemm_tc<1><<<gridG, 128, GEMM_SMEM>>>(xc, wc, bk, kp, 1.0f);
    cvt_tf32<<<NW4 / 256, 256>>>((const float4*)Wv, (float4*)wc, NW4);
    gemm_tc<1><<<gridG, 128, GEMM_SMEM>>>(xc, wc, bv, vp, 1.0f);

    const dim3 gridA(SEQ / AQ, BH);              // (16, 32)
    attn_kernel<<<gridA, 256, ATTN_SMEM>>>(qp, kp, vp, ap);

    cvt_tf32<<<NW4 / 256, 256>>>((const float4*)Wo, (float4*)wc, NW4);
    gemm_tc<0><<<gridG, 128, GEMM_SMEM>>>(ap, wc, bo, out, 1.0f);
}

// round 13
// speedup vs baseline: 2.0107x; 1.8651x over previous
#include <cuda_runtime.h>
#include <cuda_fp16.h>
#include <cstdint>

#define D_MODEL 1024
#define SEQ     2048
#define BATCH   2
#define NHEAD   16
#define HD      64
#define MTOT    (BATCH * SEQ)   // 4096
#define BH      (BATCH * NHEAD) // 32

// ---- GEMM tiling (fp16 mma.sync m16n8k16) ----
#define BM 128
#define BN 128
#define GBK 64                    // halves per k-tile
#define GKI (D_MODEL / GBK)       // 16
#define AS_STRIDE 72              // halves per A smem row
#define BS_STRIDE 72              // halves per B smem row (W transposed [n][k])
#define AS_HALF (BM * AS_STRIDE)  // 9216
#define BS_HALF (BN * BS_STRIDE)  // 9216
#define STAGE_HALF (AS_HALF + BS_HALF)
#define GEMM_SMEM (2 * STAGE_HALF * 2)   // 73728 bytes

// ---- attention tiling (R12 structure, fp16 operands) ----
#define AQ 128
#define AK 64
#define QS_STRIDE 72
#define PS_STRIDE 72              // P / K union
#define VS_STRIDE 72
#define ATTN_SMEM ((AQ * QS_STRIDE + AQ * PS_STRIDE + AK * VS_STRIDE) * 2) // 46080 B

// ---- scratch ----
__device__ __align__(1024) __half g_Qh[(size_t)BH * SEQ * HD];
__device__ __align__(1024) __half g_Kh[(size_t)BH * SEQ * HD];
__device__ __align__(1024) __half g_Vh[(size_t)BH * SEQ * HD];
__device__ __align__(1024) __half g_Ah[(size_t)MTOT * D_MODEL];
__device__ __align__(1024) __half g_Xh[(size_t)MTOT * D_MODEL];
__device__ __align__(1024) __half g_Wh[(size_t)D_MODEL * D_MODEL]; // transposed [n][k]

__device__ __forceinline__ uint32_t s2u(const void* p) {
    uint32_t a;
    asm("{ .reg .u64 t; cvta.to.shared.u64 t, %1; cvt.u32.u64 %0, t; }" : "=r"(a) : "l"(p));
    return a;
}

#define CP_ASYNC16(dst, src) \
    asm volatile("cp.async.ca.shared.global [%0], [%1], 16;" :: "r"(dst), "l"(src) : "memory")
#define CP_COMMIT()  asm volatile("cp.async.commit_group;" ::: "memory")
#define CP_WAIT(N)   asm volatile("cp.async.wait_group %0;" :: "n"(N) : "memory")

__device__ __forceinline__ void mma_f16(float* d, const uint32_t* a, const uint32_t* b) {
    asm volatile(
        "mma.sync.aligned.m16n8k16.row.col.f32.f16.f16.f32 "
        "{%0,%1,%2,%3}, {%4,%5,%6,%7}, {%8,%9}, {%0,%1,%2,%3};"
        : "+f"(d[0]), "+f"(d[1]), "+f"(d[2]), "+f"(d[3])
        : "r"(a[0]), "r"(a[1]), "r"(a[2]), "r"(a[3]), "r"(b[0]), "r"(b[1]));
}

#define LDSM_X2_TRANS(r0, r1, addr) \
    asm volatile("ldmatrix.sync.aligned.m8n8.x2.trans.shared.b16 {%0,%1}, [%2];" \
                 : "=r"(r0), "=r"(r1) : "r"(addr))

__device__ __forceinline__ uint32_t h2u(__half2 h) {
    uint32_t u;
    memcpy(&u, &h, 4);
    return u;
}

// ---------------------------------------------------------------------------
// fp32 -> fp16 straight copy (activations)
// ---------------------------------------------------------------------------
__global__ void __launch_bounds__(256) cvt_xh(const float4* __restrict__ src,
                                              uint2* __restrict__ dst, int n4)
{
    const int i = blockIdx.x * 256 + threadIdx.x;
    if (i < n4) {
        const float4 v = src[i];
        uint2 o;
        o.x = h2u(__floats2half2_rn(v.x, v.y));
        o.y = h2u(__floats2half2_rn(v.z, v.w));
        dst[i] = o;
    }
}

// ---------------------------------------------------------------------------
// W [k][n] fp32 -> Wh [n][k] fp16 (tiled transpose through smem)
// Block 256, grid (16,16): tile 64x64.
// ---------------------------------------------------------------------------
__global__ void __launch_bounds__(256) cvt_wh(const float* __restrict__ W,
                                              __half* __restrict__ Wh)
{
    __shared__ __half T[64 * 72];
    const int t = threadIdx.x;
    const int n0 = blockIdx.x * 64, k0 = blockIdx.y * 64;

#pragma unroll
    for (int it = 0; it < 4; it++) {
        const int r = (t >> 4) + it * 16;     // k-row 0..63
        const int c4 = (t & 15) * 4;          // n col
        const float4 v = *(const float4*)&W[(size_t)(k0 + r) * D_MODEL + n0 + c4];
        T[(c4 + 0) * 72 + r] = __float2half_rn(v.x);
        T[(c4 + 1) * 72 + r] = __float2half_rn(v.y);
        T[(c4 + 2) * 72 + r] = __float2half_rn(v.z);
        T[(c4 + 3) * 72 + r] = __float2half_rn(v.w);
    }
    __syncthreads();
#pragma unroll
    for (int it = 0; it < 2; it++) {
        const int rn = t >> 2;                // n-row 0..63
        const int u = (t & 3) + it * 4;       // 0..7
        const uint4 val = *(const uint4*)&T[rn * 72 + u * 8];
        *(uint4*)&Wh[(size_t)(n0 + rn) * D_MODEL + k0 + u * 8] = val;
    }
}

// ---------------------------------------------------------------------------
// fp16 mma.sync GEMM: out = A[4096,1024] * W + bias.  W pre-transposed [n][k].
// MODE 0: fp32 row-major out. MODE 1: fp16 scatter to [bh, t, hd], *scale.
// 128 threads = 4 warps (2x2); warp tile 64x64.
// ---------------------------------------------------------------------------
template <int MODE>
__global__ void __launch_bounds__(128) gemm_tc(
    const __half* __restrict__ A, const __half* __restrict__ W,
    const float* __restrict__ bias, void* __restrict__ outv, float scale)
{
    extern __shared__ __align__(16) __half smem[];
    __half* As[2] = { smem, smem + STAGE_HALF };
    __half* Bs[2] = { smem + AS_HALF, smem + STAGE_HALF + AS_HALF };

    const int tid = threadIdx.x;
    const int wid = tid >> 5, lane = tid & 31;
    const int wm = wid >> 1, wn = wid & 1;
    const int grp = lane >> 2, tg = lane & 3;
    const int nblk = blockIdx.x, mblk = blockIdx.y;

    const __half* Ag = A + (size_t)mblk * BM * D_MODEL;
    const __half* Wg = W + (size_t)nblk * BN * D_MODEL;

    auto load_stage = [&](int s, int k0) {
        __half* as = As[s];
        __half* bs = Bs[s];
#pragma unroll
        for (int j = 0; j < 8; j++) {          // A: 128 rows x 64 halves = 1024 chunks
            const int c = tid + j * 128;
            const int r = c >> 3, q = c & 7;
            CP_ASYNC16(s2u(&as[r * AS_STRIDE + q * 8]),
                       &Ag[(size_t)r * D_MODEL + k0 + q * 8]);
        }
#pragma unroll
        for (int j = 0; j < 8; j++) {          // B: 128 n-rows x 64 halves
            const int c = tid + j * 128;
            const int r = c >> 3, q = c & 7;
            CP_ASYNC16(s2u(&bs[r * BS_STRIDE + q * 8]),
                       &Wg[(size_t)r * D_MODEL + k0 + q * 8]);
        }
        CP_COMMIT();
    };

    float acc[4][8][4];
#pragma unroll
    for (int i = 0; i < 4; i++)
#pragma unroll
        for (int j = 0; j < 8; j++)
#pragma unroll
            for (int r = 0; r < 4; r++) acc[i][j][r] = 0.0f;

    load_stage(0, 0);

    for (int kt = 0; kt < GKI; kt++) {
        if (kt + 1 < GKI) {
            load_stage((kt + 1) & 1, (kt + 1) * GBK);
            CP_WAIT(1);
        } else {
            CP_WAIT(0);
        }
        __syncthreads();

        const __half* as = As[kt & 1];
        const __half* bs = Bs[kt & 1];
#pragma unroll
        for (int kk = 0; kk < GBK; kk += 16) {
            uint32_t af[4][4], bf[8][2];
#pragma unroll
            for (int mi = 0; mi < 4; mi++) {
                const int r0 = wm * 64 + mi * 16 + grp;
                af[mi][0] = *(const uint32_t*)&as[r0 * AS_STRIDE + kk + 2 * tg];
                af[mi][1] = *(const uint32_t*)&as[(r0 + 8) * AS_STRIDE + kk + 2 * tg];
                af[mi][2] = *(const uint32_t*)&as[r0 * AS_STRIDE + kk + 2 * tg + 8];
                af[mi][3] = *(const uint32_t*)&as[(r0 + 8) * AS_STRIDE + kk + 2 * tg + 8];
            }
#pragma unroll
            for (int nj = 0; nj < 8; nj++) {
                const int n0 = wn * 64 + nj * 8 + grp;
                bf[nj][0] = *(const uint32_t*)&bs[n0 * BS_STRIDE + kk + 2 * tg];
                bf[nj][1] = *(const uint32_t*)&bs[n0 * BS_STRIDE + kk + 2 * tg + 8];
            }
#pragma unroll
            for (int mi = 0; mi < 4; mi++)
#pragma unroll
                for (int nj = 0; nj < 8; nj++)
                    mma_f16(acc[mi][nj], af[mi], bf[nj]);
        }
        __syncthreads();
    }

#pragma unroll
    for (int mi = 0; mi < 4; mi++) {
#pragma unroll
        for (int half_ = 0; half_ < 2; half_++) {
            const int m = mblk * BM + wm * 64 + mi * 16 + grp + half_ * 8;
#pragma unroll
            for (int nj = 0; nj < 8; nj++) {
                const int n = nblk * BN + wn * 64 + nj * 8 + 2 * tg;
                const float vx = acc[mi][nj][half_ * 2 + 0] + bias[n];
                const float vy = acc[mi][nj][half_ * 2 + 1] + bias[n + 1];
                if (MODE == 0) {
                    float2 v = { vx, vy };
                    *(float2*)&((float*)outv)[(size_t)m * D_MODEL + n] = v;
                } else {
                    const __half2 hv = __floats2half2_rn(vx * scale, vy * scale);
                    const int bb = m >> 11, t = m & (SEQ - 1);
                    const int hh = n >> 6, hd = n & (HD - 1);
                    *(__half2*)&((__half*)outv)[(((size_t)(bb * NHEAD + hh)) * SEQ + t) * HD + hd] = hv;
                }
            }
        }
    }
}

// ---------------------------------------------------------------------------
// fp16 mma.sync flash attention (R12 structure).
// Q/K/V fp16 [bh, SEQ, HD]; Q pre-scaled 0.125. Out: g_Ah fp16 [4096,1024].
// CTA: 128 q-rows x 1 bh; 8 warps; warp tile 16 q-rows x 64 keys.
// Smem: Qs[128][72] | Ps[128][72] (rows 0..63 double as K) | Vs[64][72].
// PV B-frags via ldmatrix.x2.trans from row-major V.
// ---------------------------------------------------------------------------
__global__ void __launch_bounds__(256, 2) attn_kernel(
    const __half* __restrict__ Q, const __half* __restrict__ K,
    const __half* __restrict__ V, __half* __restrict__ out)
{
    extern __shared__ __align__(16) __half sh[];
    __half* Qs = sh;                         // [128][72]
    __half* Ps = sh + AQ * QS_STRIDE;        // [128][72]; K = rows 0..63
    __half* Vs = Ps + AQ * PS_STRIDE;        // [64][72]

    const int tid = threadIdx.x;
    const int w = tid >> 5, lane = tid & 31;
    const int grp = lane >> 2, tg = lane & 3;
    const int bh = blockIdx.y;
    const int q0 = blockIdx.x * AQ;

    const __half* Qp = Q + ((size_t)bh * SEQ + q0) * HD;
    const __half* Kp = K + (size_t)bh * SEQ * HD;
    const __half* Vp = V + (size_t)bh * SEQ * HD;

    const uint32_t vsb = s2u(Vs);

    // Load Q tile (pure copy; pre-scaled/rounded by projection GEMM)
#pragma unroll
    for (int it = 0; it < 4; it++) {
        const int idx = tid + it * 256;      // 1024 x 16B
        const int r = idx >> 3, c8 = (idx & 7) * 8;
        *(uint4*)&Qs[r * QS_STRIDE + c8] = *(const uint4*)&Qp[(size_t)r * HD + c8];
    }

    float o[8][4];
#pragma unroll
    for (int nj = 0; nj < 8; nj++)
#pragma unroll
        for (int r = 0; r < 4; r++) o[nj][r] = 0.0f;
    float m_lo = -1e30f, m_hi = -1e30f, l_lo = 0.0f, l_hi = 0.0f;

    const int row0 = w * 16 + grp;

    for (int kt = 0; kt < SEQ; kt += AK) {
        // K tile -> Ps rows 0..63; V tile -> Vs (row-major copies)
#pragma unroll
        for (int it = 0; it < 2; it++) {
            const int idx = tid + it * 256;  // 512 x 16B per tensor
            const int r = idx >> 3, c8 = (idx & 7) * 8;
            *(uint4*)&Ps[r * PS_STRIDE + c8] = *(const uint4*)&Kp[(size_t)(kt + r) * HD + c8];
            *(uint4*)&Vs[r * VS_STRIDE + c8] = *(const uint4*)&Vp[(size_t)(kt + r) * HD + c8];
        }
        __syncthreads();

        // S = Q * K^T  (16 rows x 64 keys; k16 steps)
        float s[8][4];
#pragma unroll
        for (int nj = 0; nj < 8; nj++)
#pragma unroll
            for (int r = 0; r < 4; r++) s[nj][r] = 0.0f;

#pragma unroll
        for (int kk = 0; kk < HD; kk += 16) {
            uint32_t af[4], bf[8][2];
            af[0] = *(const uint32_t*)&Qs[row0 * QS_STRIDE + kk + 2 * tg];
            af[1] = *(const uint32_t*)&Qs[(row0 + 8) * QS_STRIDE + kk + 2 * tg];
            af[2] = *(const uint32_t*)&Qs[row0 * QS_STRIDE + kk + 2 * tg + 8];
            af[3] = *(const uint32_t*)&Qs[(row0 + 8) * QS_STRIDE + kk + 2 * tg + 8];
#pragma unroll
            for (int nj = 0; nj < 8; nj++) {
                const int n0 = nj * 8 + grp;
                bf[nj][0] = *(const uint32_t*)&Ps[n0 * PS_STRIDE + kk + 2 * tg];
                bf[nj][1] = *(const uint32_t*)&Ps[n0 * PS_STRIDE + kk + 2 * tg + 8];
            }
#pragma unroll
            for (int nj = 0; nj < 8; nj++)
                mma_f16(s[nj], af, bf[nj]);
        }
        __syncthreads();   // all K reads done before P overwrites rows 0..63

        // Online softmax (rows grp -> regs 0,1 ; grp+8 -> regs 2,3)
        float mx_lo = -1e30f, mx_hi = -1e30f;
#pragma unroll
        for (int nj = 0; nj < 8; nj++) {
            mx_lo = fmaxf(mx_lo, fmaxf(s[nj][0], s[nj][1]));
            mx_hi = fmaxf(mx_hi, fmaxf(s[nj][2], s[nj][3]));
        }
#pragma unroll
        for (int off = 1; off < 4; off <<= 1) {
            mx_lo = fmaxf(mx_lo, __shfl_xor_sync(0xffffffffu, mx_lo, off));
            mx_hi = fmaxf(mx_hi, __shfl_xor_sync(0xffffffffu, mx_hi, off));
        }
        const float mn_lo = fmaxf(m_lo, mx_lo);
        const float mn_hi = fmaxf(m_hi, mx_hi);
        const float al_lo = __expf(m_lo - mn_lo);
        const float al_hi = __expf(m_hi - mn_hi);

        float rs_lo = 0.0f, rs_hi = 0.0f;
#pragma unroll
        for (int nj = 0; nj < 8; nj++) {
            s[nj][0] = __expf(s[nj][0] - mn_lo);
            s[nj][1] = __expf(s[nj][1] - mn_lo);
            s[nj][2] = __expf(s[nj][2] - mn_hi);
            s[nj][3] = __expf(s[nj][3] - mn_hi);
            rs_lo += s[nj][0] + s[nj][1];
            rs_hi += s[nj][2] + s[nj][3];
        }
#pragma unroll
        for (int off = 1; off < 4; off <<= 1) {
            rs_lo += __shfl_xor_sync(0xffffffffu, rs_lo, off);
            rs_hi += __shfl_xor_sync(0xffffffffu, rs_hi, off);
        }
        l_lo = l_lo * al_lo + rs_lo;
        l_hi = l_hi * al_hi + rs_hi;
        m_lo = mn_lo;
        m_hi = mn_hi;

        // Rescale O; store P as fp16 (own 16 rows only -> syncwarp suffices)
#pragma unroll
        for (int nj = 0; nj < 8; nj++) {
            o[nj][0] *= al_lo; o[nj][1] *= al_lo;
            o[nj][2] *= al_hi; o[nj][3] *= al_hi;
            *(__half2*)&Ps[row0 * PS_STRIDE + nj * 8 + 2 * tg] =
                __floats2half2_rn(s[nj][0], s[nj][1]);
            *(__half2*)&Ps[(row0 + 8) * PS_STRIDE + nj * 8 + 2 * tg] =
                __floats2half2_rn(s[nj][2], s[nj][3]);
        }
        __syncwarp();

        // O += P * V  (P A-frags from Ps; V B-frags via ldmatrix.trans)
#pragma unroll
        for (int kk = 0; kk < AK; kk += 16) {
            uint32_t af[4];
            af[0] = *(const uint32_t*)&Ps[row0 * PS_STRIDE + kk + 2 * tg];
            af[1] = *(const uint32_t*)&Ps[(row0 + 8) * PS_STRIDE + kk + 2 * tg];
            af[2] = *(const uint32_t*)&Ps[row0 * PS_STRIDE + kk + 2 * tg + 8];
            af[3] = *(const uint32_t*)&Ps[(row0 + 8) * PS_STRIDE + kk + 2 * tg + 8];
#pragma unroll
            for (int nj = 0; nj < 8; nj++) {
                uint32_t b0, b1;
                const uint32_t addr = vsb +
                    (uint32_t)(((kk + (lane & 15)) * VS_STRIDE + nj * 8) * 2);
                LDSM_X2_TRANS(b0, b1, addr);
                uint32_t bf[2] = { b0, b1 };
                mma_f16(o[nj], af, bf);
            }
        }
        __syncthreads();   // P/V reads done before next tile overwrites
    }

    // Normalize, convert to fp16, scatter to [4096, 1024]
    const int bb = bh >> 4;
    const int hh = bh & (NHEAD - 1);
    const float inv_lo = 1.0f / l_lo;
    const float inv_hi = 1.0f / l_hi;
    const int grow_lo = bb * SEQ + q0 + row0;
    const int colb = hh * HD;
#pragma unroll
    for (int nj = 0; nj < 8; nj++) {
        const int col = colb + nj * 8 + 2 * tg;
        *(__half2*)&out[(size_t)grow_lo * D_MODEL + col] =
            __floats2half2_rn(o[nj][0] * inv_lo, o[nj][1] * inv_lo);
        *(__half2*)&out[(size_t)(grow_lo + 8) * D_MODEL + col] =
            __floats2half2_rn(o[nj][2] * inv_hi, o[nj][3] * inv_hi);
    }
}

// ---------------------------------------------------------------------------
extern "C" void kernel_launch(void* const* d_in, const int* in_sizes, int n_in,
                              void* d_out, int out_size)
{
    (void)in_sizes; (void)n_in; (void)out_size;
    const float* x  = (const float*)d_in[0];
    const float* Wq = (const float*)d_in[1];
    const float* bq = (const float*)d_in[2];
    const float* Wk = (const float*)d_in[3];
    const float* bk = (const float*)d_in[4];
    const float* Wv = (const float*)d_in[5];
    const float* bv = (const float*)d_in[6];
    const float* Wo = (const float*)d_in[7];
    const float* bo = (const float*)d_in[8];
    float* out = (float*)d_out;

    __half *qp, *kp, *vp, *ap, *xh, *wh;
    cudaGetSymbolAddress((void**)&qp, g_Qh);
    cudaGetSymbolAddress((void**)&kp, g_Kh);
    cudaGetSymbolAddress((void**)&vp, g_Vh);
    cudaGetSymbolAddress((void**)&ap, g_Ah);
    cudaGetSymbolAddress((void**)&xh, g_Xh);
    cudaGetSymbolAddress((void**)&wh, g_Wh);

    cudaFuncSetAttribute(gemm_tc<0>, cudaFuncAttributeMaxDynamicSharedMemorySize, GEMM_SMEM);
    cudaFuncSetAttribute(gemm_tc<1>, cudaFuncAttributeMaxDynamicSharedMemorySize, GEMM_SMEM);
    cudaFuncSetAttribute(attn_kernel, cudaFuncAttributeMaxDynamicSharedMemorySize, ATTN_SMEM);

    const int NX4 = MTOT * D_MODEL / 4;          // 1,048,576
    const dim3 gridG(D_MODEL / BN, MTOT / BM);   // (8, 32)
    const dim3 gridW(16, 16);

    cvt_xh<<<NX4 / 256, 256>>>((const float4*)x, (uint2*)xh, NX4);

    cvt_wh<<<gridW, 256>>>(Wq, wh);
    gemm_tc<1><<<gridG, 128, GEMM_SMEM>>>(xh, wh, bq, qp, 0.125f);
    cvt_wh<<<gridW, 256>>>(Wk, wh);
    gemm_tc<1><<<gridG, 128, GEMM_SMEM>>>(xh, wh, bk, kp, 1.0f);
    cvt_wh<<<gridW, 256>>>(Wv, wh);
    gemm_tc<1><<<gridG, 128, GEMM_SMEM>>>(xh, wh, bv, vp, 1.0f);

    const dim3 gridA(SEQ / AQ, BH);              // (16, 32)
    attn_kernel<<<gridA, 256, ATTN_SMEM>>>(qp, kp, vp, ap);

    cvt_wh<<<gridW, 256>>>(Wo, wh);
    gemm_tc<0><<<gridG, 128, GEMM_SMEM>>>(ap, wh, bo, out, 1.0f);
}

// round 14
// speedup vs baseline: 2.0165x; 1.0029x over previous
#include <cuda_runtime.h>
#include <cuda_fp16.h>
#include <cstdint>

#define D_MODEL 1024
#define SEQ     2048
#define BATCH   2
#define NHEAD   16
#define HD      64
#define MTOT    (BATCH * SEQ)   // 4096
#define BH      (BATCH * NHEAD) // 32

// ---- GEMM tiling (fp16 mma.sync m16n8k16) ----
#define BM 128
#define BN 128
#define GBK 64                    // halves per k-tile
#define GKI (D_MODEL / GBK)       // 16
#define NSTG 3
#define AS_STRIDE 72
#define BS_STRIDE 72
#define AS_HALF (BM * AS_STRIDE)  // 9216
#define BS_HALF (BN * BS_STRIDE)  // 9216
#define STAGE_HALF (AS_HALF + BS_HALF)
#define GEMM_SMEM (NSTG * STAGE_HALF * 2)   // 110592 bytes

// ---- attention tiling (R13 structure) ----
#define AQ 128
#define AK 64
#define QS_STRIDE 72
#define PS_STRIDE 72
#define VS_STRIDE 72
#define ATTN_SMEM ((AQ * QS_STRIDE + AQ * PS_STRIDE + AK * VS_STRIDE) * 2) // 46080 B

#define WSLOT ((size_t)D_MODEL * D_MODEL)

// ---- scratch ----
__device__ __align__(1024) __half g_Qh[(size_t)BH * SEQ * HD];
__device__ __align__(1024) __half g_Kh[(size_t)BH * SEQ * HD];
__device__ __align__(1024) __half g_Vh[(size_t)BH * SEQ * HD];
__device__ __align__(1024) __half g_Ah[(size_t)MTOT * D_MODEL];
__device__ __align__(1024) __half g_Xh[(size_t)MTOT * D_MODEL];
__device__ __align__(1024) __half g_Wh[4 * WSLOT];   // [slot][n][k], slots: Wq,Wk,Wv,Wo

__device__ __forceinline__ uint32_t s2u(const void* p) {
    uint32_t a;
    asm("{ .reg .u64 t; cvta.to.shared.u64 t, %1; cvt.u32.u64 %0, t; }" : "=r"(a) : "l"(p));
    return a;
}

#define CP_ASYNC16(dst, src) \
    asm volatile("cp.async.ca.shared.global [%0], [%1], 16;" :: "r"(dst), "l"(src) : "memory")
#define CP_COMMIT()  asm volatile("cp.async.commit_group;" ::: "memory")
#define CP_WAIT(N)   asm volatile("cp.async.wait_group %0;" :: "n"(N) : "memory")

__device__ __forceinline__ void mma_f16(float* d, const uint32_t* a, const uint32_t* b) {
    asm volatile(
        "mma.sync.aligned.m16n8k16.row.col.f32.f16.f16.f32 "
        "{%0,%1,%2,%3}, {%4,%5,%6,%7}, {%8,%9}, {%0,%1,%2,%3};"
        : "+f"(d[0]), "+f"(d[1]), "+f"(d[2]), "+f"(d[3])
        : "r"(a[0]), "r"(a[1]), "r"(a[2]), "r"(a[3]), "r"(b[0]), "r"(b[1]));
}

#define LDSM_X2_TRANS(r0, r1, addr) \
    asm volatile("ldmatrix.sync.aligned.m8n8.x2.trans.shared.b16 {%0,%1}, [%2];" \
                 : "=r"(r0), "=r"(r1) : "r"(addr))

__device__ __forceinline__ uint32_t h2u(__half2 h) {
    uint32_t u;
    memcpy(&u, &h, 4);
    return u;
}

// ---------------------------------------------------------------------------
// fp32 -> fp16 straight copy (activations)
// ---------------------------------------------------------------------------
__global__ void __launch_bounds__(256) cvt_xh(const float4* __restrict__ src,
                                              uint2* __restrict__ dst, int n4)
{
    const int i = blockIdx.x * 256 + threadIdx.x;
    if (i < n4) {
        const float4 v = src[i];
        uint2 o;
        o.x = h2u(__floats2half2_rn(v.x, v.y));
        o.y = h2u(__floats2half2_rn(v.z, v.w));
        dst[i] = o;
    }
}

// ---------------------------------------------------------------------------
// All 4 weights [k][n] fp32 -> Wh[slot][n][k] fp16 in ONE launch.
// grid (16,16,4); tile 64x64 transpose through smem.
// ---------------------------------------------------------------------------
__global__ void __launch_bounds__(256) cvt_wh4(
    const float* __restrict__ W0, const float* __restrict__ W1,
    const float* __restrict__ W2, const float* __restrict__ W3,
    __half* __restrict__ Wh)
{
    __shared__ __half T[64 * 72];
    const int t = threadIdx.x;
    const int n0 = blockIdx.x * 64, k0 = blockIdx.y * 64;
    const int sl = blockIdx.z;
    const float* W = (sl == 0) ? W0 : (sl == 1) ? W1 : (sl == 2) ? W2 : W3;
    __half* dst = Wh + (size_t)sl * WSLOT;

#pragma unroll
    for (int it = 0; it < 4; it++) {
        const int r = (t >> 4) + it * 16;
        const int c4 = (t & 15) * 4;
        const float4 v = *(const float4*)&W[(size_t)(k0 + r) * D_MODEL + n0 + c4];
        T[(c4 + 0) * 72 + r] = __float2half_rn(v.x);
        T[(c4 + 1) * 72 + r] = __float2half_rn(v.y);
        T[(c4 + 2) * 72 + r] = __float2half_rn(v.z);
        T[(c4 + 3) * 72 + r] = __float2half_rn(v.w);
    }
    __syncthreads();
#pragma unroll
    for (int it = 0; it < 2; it++) {
        const int rn = t >> 2;
        const int u = (t & 3) + it * 4;
        const uint4 val = *(const uint4*)&T[rn * 72 + u * 8];
        *(uint4*)&dst[(size_t)(n0 + rn) * D_MODEL + k0 + u * 8] = val;
    }
}

// ---------------------------------------------------------------------------
// Shared GEMM mainloop (3-stage cp.async). Computes acc = A_tile * W_tile.
// ---------------------------------------------------------------------------
__device__ __forceinline__ void gemm_mainloop(
    const __half* Ag, const __half* Wg, __half* smem,
    int tid, int wm, int wn, int grp, int tg, float acc[4][8][4])
{
    __half* As[NSTG];
    __half* Bs[NSTG];
#pragma unroll
    for (int s = 0; s < NSTG; s++) {
        As[s] = smem + s * STAGE_HALF;
        Bs[s] = As[s] + AS_HALF;
    }

    auto load_stage = [&](int s, int k0) {
        __half* as = As[s];
        __half* bs = Bs[s];
#pragma unroll
        for (int j = 0; j < 8; j++) {
            const int c = tid + j * 128;
            const int r = c >> 3, q = c & 7;
            CP_ASYNC16(s2u(&as[r * AS_STRIDE + q * 8]),
                       &Ag[(size_t)r * D_MODEL + k0 + q * 8]);
        }
#pragma unroll
        for (int j = 0; j < 8; j++) {
            const int c = tid + j * 128;
            const int r = c >> 3, q = c & 7;
            CP_ASYNC16(s2u(&bs[r * BS_STRIDE + q * 8]),
                       &Wg[(size_t)r * D_MODEL + k0 + q * 8]);
        }
        CP_COMMIT();
    };

    load_stage(0, 0);
    load_stage(1, GBK);

    for (int kt = 0; kt < GKI; kt++) {
        if (kt + 2 < GKI) {
            load_stage((kt + 2) % NSTG, (kt + 2) * GBK);
            CP_WAIT(2);
        } else if (kt + 1 < GKI) {
            CP_WAIT(1);
        } else {
            CP_WAIT(0);
        }
        __syncthreads();

        const __half* as = As[kt % NSTG];
        const __half* bs = Bs[kt % NSTG];
#pragma unroll
        for (int kk = 0; kk < GBK; kk += 16) {
            uint32_t af[4][4], bf[8][2];
#pragma unroll
            for (int mi = 0; mi < 4; mi++) {
                const int r0 = wm * 64 + mi * 16 + grp;
                af[mi][0] = *(const uint32_t*)&as[r0 * AS_STRIDE + kk + 2 * tg];
                af[mi][1] = *(const uint32_t*)&as[(r0 + 8) * AS_STRIDE + kk + 2 * tg];
                af[mi][2] = *(const uint32_t*)&as[r0 * AS_STRIDE + kk + 2 * tg + 8];
                af[mi][3] = *(const uint32_t*)&as[(r0 + 8) * AS_STRIDE + kk + 2 * tg + 8];
            }
#pragma unroll
            for (int nj = 0; nj < 8; nj++) {
                const int n0 = wn * 64 + nj * 8 + grp;
                bf[nj][0] = *(const uint32_t*)&bs[n0 * BS_STRIDE + kk + 2 * tg];
                bf[nj][1] = *(const uint32_t*)&bs[n0 * BS_STRIDE + kk + 2 * tg + 8];
            }
#pragma unroll
            for (int mi = 0; mi < 4; mi++)
#pragma unroll
                for (int nj = 0; nj < 8; nj++)
                    mma_f16(acc[mi][nj], af[mi], bf[nj]);
        }
        __syncthreads();
    }
}

// ---------------------------------------------------------------------------
// Fused QKV GEMM: grid (24, 32). blockIdx.x/8 selects {W-slot, bias, dst, scale}.
// Output fp16 scattered to [bh, t, hd]; Q pre-scaled by 0.125.
// ---------------------------------------------------------------------------
__global__ void __launch_bounds__(128) gemm_qkv(
    const __half* __restrict__ A, const __half* __restrict__ Wh,
    const float* __restrict__ bq, const float* __restrict__ bk,
    const float* __restrict__ bv,
    __half* __restrict__ outq, __half* __restrict__ outk, __half* __restrict__ outv)
{
    extern __shared__ __align__(16) __half smem[];
    const int tid = threadIdx.x;
    const int wid = tid >> 5, lane = tid & 31;
    const int wm = wid >> 1, wn = wid & 1;
    const int grp = lane >> 2, tg = lane & 3;
    const int sel = blockIdx.x >> 3;             // 0=Q, 1=K, 2=V
    const int nblk = blockIdx.x & 7, mblk = blockIdx.y;

    const float* bias = (sel == 0) ? bq : (sel == 1) ? bk : bv;
    __half* out = (sel == 0) ? outq : (sel == 1) ? outk : outv;
    const float scale = (sel == 0) ? 0.125f : 1.0f;

    const __half* Ag = A + (size_t)mblk * BM * D_MODEL;
    const __half* Wg = Wh + (size_t)sel * WSLOT + (size_t)nblk * BN * D_MODEL;

    float acc[4][8][4];
#pragma unroll
    for (int i = 0; i < 4; i++)
#pragma unroll
        for (int j = 0; j < 8; j++)
#pragma unroll
            for (int r = 0; r < 4; r++) acc[i][j][r] = 0.0f;

    gemm_mainloop(Ag, Wg, smem, tid, wm, wn, grp, tg, acc);

#pragma unroll
    for (int mi = 0; mi < 4; mi++) {
#pragma unroll
        for (int half_ = 0; half_ < 2; half_++) {
            const int m = mblk * BM + wm * 64 + mi * 16 + grp + half_ * 8;
#pragma unroll
            for (int nj = 0; nj < 8; nj++) {
                const int n = nblk * BN + wn * 64 + nj * 8 + 2 * tg;
                const float vx = (acc[mi][nj][half_ * 2 + 0] + bias[n]) * scale;
                const float vy = (acc[mi][nj][half_ * 2 + 1] + bias[n + 1]) * scale;
                const __half2 hv = __floats2half2_rn(vx, vy);
                const int bb = m >> 11, t = m & (SEQ - 1);
                const int hh = n >> 6, hd = n & (HD - 1);
                *(__half2*)&out[(((size_t)(bb * NHEAD + hh)) * SEQ + t) * HD + hd] = hv;
            }
        }
    }
}

// ---------------------------------------------------------------------------
// Output GEMM: out(fp32, row-major) = A(fp16) * Wh[slot 3] + bias.
// ---------------------------------------------------------------------------
__global__ void __launch_bounds__(128) gemm_out(
    const __half* __restrict__ A, const __half* __restrict__ Wh,
    const float* __restrict__ bias, float* __restrict__ out)
{
    extern __shared__ __align__(16) __half smem[];
    const int tid = threadIdx.x;
    const int wid = tid >> 5, lane = tid & 31;
    const int wm = wid >> 1, wn = wid & 1;
    const int grp = lane >> 2, tg = lane & 3;
    const int nblk = blockIdx.x, mblk = blockIdx.y;

    const __half* Ag = A + (size_t)mblk * BM * D_MODEL;
    const __half* Wg = Wh + 3 * WSLOT + (size_t)nblk * BN * D_MODEL;

    float acc[4][8][4];
#pragma unroll
    for (int i = 0; i < 4; i++)
#pragma unroll
        for (int j = 0; j < 8; j++)
#pragma unroll
            for (int r = 0; r < 4; r++) acc[i][j][r] = 0.0f;

    gemm_mainloop(Ag, Wg, smem, tid, wm, wn, grp, tg, acc);

#pragma unroll
    for (int mi = 0; mi < 4; mi++) {
#pragma unroll
        for (int half_ = 0; half_ < 2; half_++) {
            const int m = mblk * BM + wm * 64 + mi * 16 + grp + half_ * 8;
#pragma unroll
            for (int nj = 0; nj < 8; nj++) {
                const int n = nblk * BN + wn * 64 + nj * 8 + 2 * tg;
                float2 v;
                v.x = acc[mi][nj][half_ * 2 + 0] + bias[n];
                v.y = acc[mi][nj][half_ * 2 + 1] + bias[n + 1];
                *(float2*)&out[(size_t)m * D_MODEL + n] = v;
            }
        }
    }
}

// ---------------------------------------------------------------------------
// fp16 mma.sync flash attention (R13, unchanged).
// ---------------------------------------------------------------------------
__global__ void __launch_bounds__(256, 2) attn_kernel(
    const __half* __restrict__ Q, const __half* __restrict__ K,
    const __half* __restrict__ V, __half* __restrict__ out)
{
    extern __shared__ __align__(16) __half sh[];
    __half* Qs = sh;                         // [128][72]
    __half* Ps = sh + AQ * QS_STRIDE;        // [128][72]; K = rows 0..63
    __half* Vs = Ps + AQ * PS_STRIDE;        // [64][72]

    const int tid = threadIdx.x;
    const int w = tid >> 5, lane = tid & 31;
    const int grp = lane >> 2, tg = lane & 3;
    const int bh = blockIdx.y;
    const int q0 = blockIdx.x * AQ;

    const __half* Qp = Q + ((size_t)bh * SEQ + q0) * HD;
    const __half* Kp = K + (size_t)bh * SEQ * HD;
    const __half* Vp = V + (size_t)bh * SEQ * HD;

    const uint32_t vsb = s2u(Vs);

#pragma unroll
    for (int it = 0; it < 4; it++) {
        const int idx = tid + it * 256;
        const int r = idx >> 3, c8 = (idx & 7) * 8;
        *(uint4*)&Qs[r * QS_STRIDE + c8] = *(const uint4*)&Qp[(size_t)r * HD + c8];
    }

    float o[8][4];
#pragma unroll
    for (int nj = 0; nj < 8; nj++)
#pragma unroll
        for (int r = 0; r < 4; r++) o[nj][r] = 0.0f;
    float m_lo = -1e30f, m_hi = -1e30f, l_lo = 0.0f, l_hi = 0.0f;

    const int row0 = w * 16 + grp;

    for (int kt = 0; kt < SEQ; kt += AK) {
#pragma unroll
        for (int it = 0; it < 2; it++) {
            const int idx = tid + it * 256;
            const int r = idx >> 3, c8 = (idx & 7) * 8;
            *(uint4*)&Ps[r * PS_STRIDE + c8] = *(const uint4*)&Kp[(size_t)(kt + r) * HD + c8];
            *(uint4*)&Vs[r * VS_STRIDE + c8] = *(const uint4*)&Vp[(size_t)(kt + r) * HD + c8];
        }
        __syncthreads();

        float s[8][4];
#pragma unroll
        for (int nj = 0; nj < 8; nj++)
#pragma unroll
            for (int r = 0; r < 4; r++) s[nj][r] = 0.0f;

#pragma unroll
        for (int kk = 0; kk < HD; kk += 16) {
            uint32_t af[4], bf[8][2];
            af[0] = *(const uint32_t*)&Qs[row0 * QS_STRIDE + kk + 2 * tg];
            af[1] = *(const uint32_t*)&Qs[(row0 + 8) * QS_STRIDE + kk + 2 * tg];
            af[2] = *(const uint32_t*)&Qs[row0 * QS_STRIDE + kk + 2 * tg + 8];
            af[3] = *(const uint32_t*)&Qs[(row0 + 8) * QS_STRIDE + kk + 2 * tg + 8];
#pragma unroll
            for (int nj = 0; nj < 8; nj++) {
                const int n0 = nj * 8 + grp;
                bf[nj][0] = *(const uint32_t*)&Ps[n0 * PS_STRIDE + kk + 2 * tg];
                bf[nj][1] = *(const uint32_t*)&Ps[n0 * PS_STRIDE + kk + 2 * tg + 8];
            }
#pragma unroll
            for (int nj = 0; nj < 8; nj++)
                mma_f16(s[nj], af, bf[nj]);
        }
        __syncthreads();

        float mx_lo = -1e30f, mx_hi = -1e30f;
#pragma unroll
        for (int nj = 0; nj < 8; nj++) {
            mx_lo = fmaxf(mx_lo, fmaxf(s[nj][0], s[nj][1]));
            mx_hi = fmaxf(mx_hi, fmaxf(s[nj][2], s[nj][3]));
        }
#pragma unroll
        for (int off = 1; off < 4; off <<= 1) {
            mx_lo = fmaxf(mx_lo, __shfl_xor_sync(0xffffffffu, mx_lo, off));
            mx_hi = fmaxf(mx_hi, __shfl_xor_sync(0xffffffffu, mx_hi, off));
        }
        const float mn_lo = fmaxf(m_lo, mx_lo);
        const float mn_hi = fmaxf(m_hi, mx_hi);
        const float al_lo = __expf(m_lo - mn_lo);
        const float al_hi = __expf(m_hi - mn_hi);

        float rs_lo = 0.0f, rs_hi = 0.0f;
#pragma unroll
        for (int nj = 0; nj < 8; nj++) {
            s[nj][0] = __expf(s[nj][0] - mn_lo);
            s[nj][1] = __expf(s[nj][1] - mn_lo);
            s[nj][2] = __expf(s[nj][2] - mn_hi);
            s[nj][3] = __expf(s[nj][3] - mn_hi);
            rs_lo += s[nj][0] + s[nj][1];
            rs_hi += s[nj][2] + s[nj][3];
        }
#pragma unroll
        for (int off = 1; off < 4; off <<= 1) {
            rs_lo += __shfl_xor_sync(0xffffffffu, rs_lo, off);
            rs_hi += __shfl_xor_sync(0xffffffffu, rs_hi, off);
        }
        l_lo = l_lo * al_lo + rs_lo;
        l_hi = l_hi * al_hi + rs_hi;
        m_lo = mn_lo;
        m_hi = mn_hi;

#pragma unroll
        for (int nj = 0; nj < 8; nj++) {
            o[nj][0] *= al_lo; o[nj][1] *= al_lo;
            o[nj][2] *= al_hi; o[nj][3] *= al_hi;
            *(__half2*)&Ps[row0 * PS_STRIDE + nj * 8 + 2 * tg] =
                __floats2half2_rn(s[nj][0], s[nj][1]);
            *(__half2*)&Ps[(row0 + 8) * PS_STRIDE + nj * 8 + 2 * tg] =
                __floats2half2_rn(s[nj][2], s[nj][3]);
        }
        __syncwarp();

#pragma unroll
        for (int kk = 0; kk < AK; kk += 16) {
            uint32_t af[4];
            af[0] = *(const uint32_t*)&Ps[row0 * PS_STRIDE + kk + 2 * tg];
            af[1] = *(const uint32_t*)&Ps[(row0 + 8) * PS_STRIDE + kk + 2 * tg];
            af[2] = *(const uint32_t*)&Ps[row0 * PS_STRIDE + kk + 2 * tg + 8];
            af[3] = *(const uint32_t*)&Ps[(row0 + 8) * PS_STRIDE + kk + 2 * tg + 8];
#pragma unroll
            for (int nj = 0; nj < 8; nj++) {
                uint32_t b0, b1;
                const uint32_t addr = vsb +
                    (uint32_t)(((kk + (lane & 15)) * VS_STRIDE + nj * 8) * 2);
                LDSM_X2_TRANS(b0, b1, addr);
                uint32_t bf[2] = { b0, b1 };
                mma_f16(o[nj], af, bf);
            }
        }
        __syncthreads();
    }

    const int bb = bh >> 4;
    const int hh = bh & (NHEAD - 1);
    const float inv_lo = 1.0f / l_lo;
    const float inv_hi = 1.0f / l_hi;
    const int grow_lo = bb * SEQ + q0 + row0;
    const int colb = hh * HD;
#pragma unroll
    for (int nj = 0; nj < 8; nj++) {
        const int col = colb + nj * 8 + 2 * tg;
        *(__half2*)&out[(size_t)grow_lo * D_MODEL + col] =
            __floats2half2_rn(o[nj][0] * inv_lo, o[nj][1] * inv_lo);
        *(__half2*)&out[(size_t)(grow_lo + 8) * D_MODEL + col] =
            __floats2half2_rn(o[nj][2] * inv_hi, o[nj][3] * inv_hi);
    }
}

// ---------------------------------------------------------------------------
extern "C" void kernel_launch(void* const* d_in, const int* in_sizes, int n_in,
                              void* d_out, int out_size)
{
    (void)in_sizes; (void)n_in; (void)out_size;
    const float* x  = (const float*)d_in[0];
    const float* Wq = (const float*)d_in[1];
    const float* bq = (const float*)d_in[2];
    const float* Wk = (const float*)d_in[3];
    const float* bk = (const float*)d_in[4];
    const float* Wv = (const float*)d_in[5];
    const float* bv = (const float*)d_in[6];
    const float* Wo = (const float*)d_in[7];
    const float* bo = (const float*)d_in[8];
    float* out = (float*)d_out;

    __half *qp, *kp, *vp, *ap, *xh, *wh;
    cudaGetSymbolAddress((void**)&qp, g_Qh);
    cudaGetSymbolAddress((void**)&kp, g_Kh);
    cudaGetSymbolAddress((void**)&vp, g_Vh);
    cudaGetSymbolAddress((void**)&ap, g_Ah);
    cudaGetSymbolAddress((void**)&xh, g_Xh);
    cudaGetSymbolAddress((void**)&wh, g_Wh);

    cudaFuncSetAttribute(gemm_qkv, cudaFuncAttributeMaxDynamicSharedMemorySize, GEMM_SMEM);
    cudaFuncSetAttribute(gemm_out, cudaFuncAttributeMaxDynamicSharedMemorySize, GEMM_SMEM);
    cudaFuncSetAttribute(attn_kernel, cudaFuncAttributeMaxDynamicSharedMemorySize, ATTN_SMEM);

    const int NX4 = MTOT * D_MODEL / 4;          // 1,048,576

    cvt_xh<<<NX4 / 256, 256>>>((const float4*)x, (uint2*)xh, NX4);
    cvt_wh4<<<dim3(16, 16, 4), 256>>>(Wq, Wk, Wv, Wo, wh);

    gemm_qkv<<<dim3(24, 32), 128, GEMM_SMEM>>>(xh, wh, bq, bk, bv, qp, kp, vp);

    const dim3 gridA(SEQ / AQ, BH);              // (16, 32)
    attn_kernel<<<gridA, 256, ATTN_SMEM>>>(qp, kp, vp, ap);

    gemm_out<<<dim3(8, 32), 128, GEMM_SMEM>>>(ap, wh, bo, out);
}